// round 2
// baseline (speedup 1.0000x reference)
#include <cuda_runtime.h>
#include <math.h>

// Problem constants
#define B_SZ 4
#define SEQ 2048
#define DM 1024
#define NHEAD 16
#define HD 64
#define DFF 4096
#define M_ROWS (B_SZ * SEQ)   // 8192

// ---------------------------------------------------------------------------
// Scratch buffers (no cudaMalloc allowed -> __device__ globals)
// ---------------------------------------------------------------------------
__device__ float g_xn[M_ROWS * DM];
__device__ float g_q[M_ROWS * DM];
__device__ float g_k[M_ROWS * DM];
__device__ float g_v[M_ROWS * DM];
__device__ float g_ao[M_ROWS * DM];
__device__ float g_x1[M_ROWS * DM];
__device__ float g_gate[M_ROWS * DFF];
__device__ float g_h[M_ROWS * DFF];

// ---------------------------------------------------------------------------
// RMSNorm: one block per row of 1024 floats, 256 threads x 4 floats
// ---------------------------------------------------------------------------
__global__ __launch_bounds__(256)
void rmsnorm_kernel(const float* __restrict__ x, const float* __restrict__ w,
                    float* __restrict__ y) {
    int row = blockIdx.x;
    int tid = threadIdx.x;
    const float* xr = x + (size_t)row * DM;
    float4 v = *(const float4*)(xr + tid * 4);
    float s = v.x * v.x + v.y * v.y + v.z * v.z + v.w * v.w;
    #pragma unroll
    for (int off = 16; off; off >>= 1)
        s += __shfl_xor_sync(0xffffffffu, s, off);
    __shared__ float red[8];
    if ((tid & 31) == 0) red[tid >> 5] = s;
    __syncthreads();
    float tot = red[0] + red[1] + red[2] + red[3] +
                red[4] + red[5] + red[6] + red[7];
    float inv = rsqrtf(tot * (1.0f / DM) + 1e-5f);
    float4 wv = *(const float4*)(w + tid * 4);
    v.x *= inv * wv.x; v.y *= inv * wv.y; v.z *= inv * wv.z; v.w *= inv * wv.w;
    *(float4*)(y + (size_t)row * DM + tid * 4) = v;
}

// ---------------------------------------------------------------------------
// RoPE in-place on q and k. Layout [b, s, h, d] => row m = b*SEQ+s, col h*64+d.
// One thread per (row, head, pair).
// ---------------------------------------------------------------------------
__global__ __launch_bounds__(256)
void rope_kernel(float* __restrict__ q, float* __restrict__ k) {
    int idx = blockIdx.x * blockDim.x + threadIdx.x;   // M_ROWS*512
    if (idx >= M_ROWS * 512) return;
    int m  = idx >> 9;
    int pir = idx & 511;          // pair within row
    int h  = pir >> 5;            // head
    int pp = pir & 31;            // pair index within head (0..31)
    int s  = m & (SEQ - 1);
    // inv_freq = 10000^(-2*pp/64)
    float inv_freq = expf(-(float)(2 * pp) * (9.210340371976184f / 64.0f));
    float ang = (float)s * inv_freq;
    float sn, cs;
    sincosf(ang, &sn, &cs);
    size_t off = (size_t)m * DM + h * HD + 2 * pp;
    float qe = q[off], qo = q[off + 1];
    q[off]     = qe * cs - qo * sn;
    q[off + 1] = qo * cs + qe * sn;
    float ke = k[off], ko = k[off + 1];
    k[off]     = ke * cs - ko * sn;
    k[off + 1] = ko * cs + ke * sn;
}

// ---------------------------------------------------------------------------
// SGEMM: C[M,N] = A[M,K] * W[N,K]^T  (+ epilogue)
// 128x128 tile, BK=8, 256 threads, 8x8 per thread. M=8192 via gridDim.y=64.
// EPI: 0 = none, 1 = C = AB + aux, 2 = C = silu(AB) * aux
// ---------------------------------------------------------------------------
template <int EPI>
__global__ __launch_bounds__(256)
void sgemm_kernel(const float* __restrict__ A, const float* __restrict__ W,
                  float* __restrict__ C, const float* __restrict__ aux,
                  int N, int K) {
    __shared__ float As[8][128];
    __shared__ float Bs[8][128];
    int tid = threadIdx.x;
    int m0 = blockIdx.y * 128;
    int n0 = blockIdx.x * 128;
    int lr = tid >> 1;            // 0..127
    int lc = (tid & 1) << 2;      // 0 or 4
    int tx = tid & 15, ty = tid >> 4;

    float acc[8][8];
    #pragma unroll
    for (int i = 0; i < 8; ++i)
        #pragma unroll
        for (int j = 0; j < 8; ++j) acc[i][j] = 0.0f;

    const float* Ag = A + (size_t)(m0 + lr) * K + lc;
    const float* Wg = W + (size_t)(n0 + lr) * K + lc;

    for (int k0 = 0; k0 < K; k0 += 8) {
        float4 av = *(const float4*)(Ag + k0);
        float4 bv = *(const float4*)(Wg + k0);
        __syncthreads();
        As[lc + 0][lr] = av.x; As[lc + 1][lr] = av.y;
        As[lc + 2][lr] = av.z; As[lc + 3][lr] = av.w;
        Bs[lc + 0][lr] = bv.x; Bs[lc + 1][lr] = bv.y;
        Bs[lc + 2][lr] = bv.z; Bs[lc + 3][lr] = bv.w;
        __syncthreads();
        #pragma unroll
        for (int kk = 0; kk < 8; ++kk) {
            float a[8], b[8];
            *(float4*)(a)     = *(const float4*)&As[kk][ty * 8];
            *(float4*)(a + 4) = *(const float4*)&As[kk][ty * 8 + 4];
            *(float4*)(b)     = *(const float4*)&Bs[kk][tx * 8];
            *(float4*)(b + 4) = *(const float4*)&Bs[kk][tx * 8 + 4];
            #pragma unroll
            for (int i = 0; i < 8; ++i)
                #pragma unroll
                for (int j = 0; j < 8; ++j)
                    acc[i][j] += a[i] * b[j];
        }
    }

    #pragma unroll
    for (int i = 0; i < 8; ++i) {
        size_t rowoff = (size_t)(m0 + ty * 8 + i) * N + n0 + tx * 8;
        #pragma unroll
        for (int j = 0; j < 8; ++j) {
            float u = acc[i][j];
            float r;
            if (EPI == 0) {
                r = u;
            } else if (EPI == 1) {
                r = u + aux[rowoff + j];
            } else {
                float sg = 1.0f / (1.0f + __expf(-u));
                r = u * sg * aux[rowoff + j];
            }
            C[rowoff + j] = r;
        }
    }
}

// ---------------------------------------------------------------------------
// Flash attention (fp32, causal). One block = 64 query rows of one (b,h).
// gridDim = (SEQ/64, B*H). 256 threads as 16x16, each 4x4 of the 64x64 tile.
// Dynamic smem: Qs[64][64] + KVs[64][65] + Ps[64][64] = 49408 bytes.
// ---------------------------------------------------------------------------
__global__ __launch_bounds__(256)
void flash_kernel(const float* __restrict__ q, const float* __restrict__ k,
                  const float* __restrict__ v, float* __restrict__ o) {
    extern __shared__ float sm[];
    float* Qs  = sm;                 // 64*64
    float* KVs = sm + 4096;          // 64*65 (K then V, reused)
    float* Ps  = sm + 4096 + 4160;   // 64*64

    int tid = threadIdx.x;
    int tx = tid & 15, ty = tid >> 4;
    int qb = blockIdx.x;
    int bh = blockIdx.y;
    int b = bh >> 4, h = bh & 15;
    int i0 = qb * 64;
    size_t base = ((size_t)b * SEQ) * DM + h * HD;

    // Load Q tile
    for (int t = tid; t < 1024; t += 256) {
        int r = t >> 4, c4 = (t & 15) << 2;
        *(float4*)(Qs + r * 64 + c4) =
            *(const float4*)(q + base + (size_t)(i0 + r) * DM + c4);
    }

    float acc[4][4];
    float mrow[4], lrow[4];
    #pragma unroll
    for (int i = 0; i < 4; ++i) {
        mrow[i] = -1e30f; lrow[i] = 0.0f;
        #pragma unroll
        for (int j = 0; j < 4; ++j) acc[i][j] = 0.0f;
    }

    for (int j = 0; j <= qb; ++j) {
        __syncthreads();   // prior V reads (and Q load on iter 0) complete
        // Load K tile (ld = 65, scalar stores)
        for (int t = tid; t < 1024; t += 256) {
            int r = t >> 4, c4 = (t & 15) << 2;
            float4 kv = *(const float4*)(k + base + (size_t)(j * 64 + r) * DM + c4);
            float* d = KVs + r * 65 + c4;
            d[0] = kv.x; d[1] = kv.y; d[2] = kv.z; d[3] = kv.w;
        }
        __syncthreads();

        // S = Q K^T  (64x64x64)
        float sreg[4][4];
        #pragma unroll
        for (int i = 0; i < 4; ++i)
            #pragma unroll
            for (int jj = 0; jj < 4; ++jj) sreg[i][jj] = 0.0f;
        #pragma unroll 16
        for (int d = 0; d < 64; ++d) {
            float a[4], bb[4];
            #pragma unroll
            for (int i = 0; i < 4; ++i)  a[i]  = Qs[(ty * 4 + i) * 64 + d];
            #pragma unroll
            for (int jj = 0; jj < 4; ++jj) bb[jj] = KVs[(tx * 4 + jj) * 65 + d];
            #pragma unroll
            for (int i = 0; i < 4; ++i)
                #pragma unroll
                for (int jj = 0; jj < 4; ++jj)
                    sreg[i][jj] += a[i] * bb[jj];
        }

        // scale + causal mask (only the diagonal tile needs masking)
        bool diag = (j == qb);
        #pragma unroll
        for (int i = 0; i < 4; ++i)
            #pragma unroll
            for (int jj = 0; jj < 4; ++jj) {
                float val = sreg[i][jj] * 0.125f;
                if (diag && (tx * 4 + jj) > (ty * 4 + i)) val = -1e30f;
                sreg[i][jj] = val;
            }

        // online softmax per row (rows owned by the 16 lanes sharing ty)
        #pragma unroll
        for (int i = 0; i < 4; ++i) {
            float rmax = fmaxf(fmaxf(sreg[i][0], sreg[i][1]),
                               fmaxf(sreg[i][2], sreg[i][3]));
            #pragma unroll
            for (int off = 8; off; off >>= 1)
                rmax = fmaxf(rmax, __shfl_xor_sync(0xffffffffu, rmax, off, 16));
            float mnew = fmaxf(mrow[i], rmax);
            float corr = __expf(mrow[i] - mnew);
            mrow[i] = mnew;
            float4 p;
            p.x = __expf(sreg[i][0] - mnew);
            p.y = __expf(sreg[i][1] - mnew);
            p.z = __expf(sreg[i][2] - mnew);
            p.w = __expf(sreg[i][3] - mnew);
            float rs = p.x + p.y + p.z + p.w;
            #pragma unroll
            for (int off = 8; off; off >>= 1)
                rs += __shfl_xor_sync(0xffffffffu, rs, off, 16);
            lrow[i] = lrow[i] * corr + rs;
            *(float4*)(Ps + (ty * 4 + i) * 64 + tx * 4) = p;
            #pragma unroll
            for (int jj = 0; jj < 4; ++jj) acc[i][jj] *= corr;
        }
        __syncthreads();   // P written, K reads done -> safe to overwrite with V

        // Load V tile
        for (int t = tid; t < 1024; t += 256) {
            int r = t >> 4, c4 = (t & 15) << 2;
            float4 vv = *(const float4*)(v + base + (size_t)(j * 64 + r) * DM + c4);
            float* d = KVs + r * 65 + c4;
            d[0] = vv.x; d[1] = vv.y; d[2] = vv.z; d[3] = vv.w;
        }
        __syncthreads();

        // O += P V  (64x64x64)
        #pragma unroll 16
        for (int c = 0; c < 64; ++c) {
            float p[4], vv[4];
            #pragma unroll
            for (int i = 0; i < 4; ++i)  p[i]  = Ps[(ty * 4 + i) * 64 + c];
            #pragma unroll
            for (int jj = 0; jj < 4; ++jj) vv[jj] = KVs[c * 65 + tx * 4 + jj];
            #pragma unroll
            for (int i = 0; i < 4; ++i)
                #pragma unroll
                for (int jj = 0; jj < 4; ++jj)
                    acc[i][jj] += p[i] * vv[jj];
        }
    }

    // Normalize and write out (layout [b,s,h,d] => same [M,1024] rows)
    #pragma unroll
    for (int i = 0; i < 4; ++i) {
        float inv = 1.0f / lrow[i];
        #pragma unroll
        for (int jj = 0; jj < 4; ++jj)
            o[base + (size_t)(i0 + ty * 4 + i) * DM + tx * 4 + jj] =
                acc[i][jj] * inv;
    }
}

// ---------------------------------------------------------------------------
// Launch
// ---------------------------------------------------------------------------
extern "C" void kernel_launch(void* const* d_in, const int* in_sizes, int n_in,
                              void* d_out, int out_size) {
    const float* x     = (const float*)d_in[0];
    const float* wq    = (const float*)d_in[1];
    const float* wk    = (const float*)d_in[2];
    const float* wv    = (const float*)d_in[3];
    const float* wo    = (const float*)d_in[4];
    const float* ln1w  = (const float*)d_in[5];
    const float* ln2w  = (const float*)d_in[6];
    const float* upw   = (const float*)d_in[7];
    const float* gatew = (const float*)d_in[8];
    const float* downw = (const float*)d_in[9];
    float* out = (float*)d_out;

    float *xn, *q, *k, *v, *ao, *x1, *gate, *hbuf;
    cudaGetSymbolAddress((void**)&xn,   g_xn);
    cudaGetSymbolAddress((void**)&q,    g_q);
    cudaGetSymbolAddress((void**)&k,    g_k);
    cudaGetSymbolAddress((void**)&v,    g_v);
    cudaGetSymbolAddress((void**)&ao,   g_ao);
    cudaGetSymbolAddress((void**)&x1,   g_x1);
    cudaGetSymbolAddress((void**)&gate, g_gate);
    cudaGetSymbolAddress((void**)&hbuf, g_h);

    cudaFuncSetAttribute(flash_kernel,
                         cudaFuncAttributeMaxDynamicSharedMemorySize, 49408);

    dim3 g1(DM / 128, M_ROWS / 128);    // (8, 64)
    dim3 g2(DFF / 128, M_ROWS / 128);   // (32, 64)

    // ln1
    rmsnorm_kernel<<<M_ROWS, 256>>>(x, ln1w, xn);
    // q, k, v projections
    sgemm_kernel<0><<<g1, 256>>>(xn, wq, q, nullptr, DM, DM);
    sgemm_kernel<0><<<g1, 256>>>(xn, wk, k, nullptr, DM, DM);
    sgemm_kernel<0><<<g1, 256>>>(xn, wv, v, nullptr, DM, DM);
    // rope on q, k
    rope_kernel<<<(M_ROWS * 512) / 256, 256>>>(q, k);
    // causal flash attention
    flash_kernel<<<dim3(SEQ / 64, B_SZ * NHEAD), 256, 49408>>>(q, k, v, ao);
    // o projection + residual
    sgemm_kernel<1><<<g1, 256>>>(ao, wo, x1, x, DM, DM);
    // ln2
    rmsnorm_kernel<<<M_ROWS, 256>>>(x1, ln2w, xn);
    // FFN: gate, then up with fused silu(up)*gate, then down + residual
    sgemm_kernel<0><<<g2, 256>>>(xn, gatew, gate, nullptr, DFF, DM);
    sgemm_kernel<2><<<g2, 256>>>(xn, upw, hbuf, gate, DFF, DM);
    sgemm_kernel<1><<<g1, 256>>>(hbuf, downw, out, x1, DM, DFF);
}

// round 3
// speedup vs baseline: 1.3343x; 1.3343x over previous
#include <cuda_runtime.h>
#include <math.h>
#include <stdint.h>

// Problem constants
#define B_SZ 4
#define SEQ 2048
#define DM 1024
#define NHEAD 16
#define HD 64
#define DFF 4096
#define M_ROWS (B_SZ * SEQ)   // 8192

// ---------------------------------------------------------------------------
// Scratch buffers (no cudaMalloc allowed -> __device__ globals)
// ---------------------------------------------------------------------------
__device__ float g_xn[M_ROWS * DM];
__device__ float g_q[M_ROWS * DM];
__device__ float g_k[M_ROWS * DM];
__device__ float g_v[M_ROWS * DM];
__device__ float g_ao[M_ROWS * DM];
__device__ float g_x1[M_ROWS * DM];
__device__ float g_gate[M_ROWS * DFF];
__device__ float g_h[M_ROWS * DFF];

// ---------------------------------------------------------------------------
// RMSNorm: one block per row of 1024 floats, 256 threads x 4 floats
// ---------------------------------------------------------------------------
__global__ __launch_bounds__(256)
void rmsnorm_kernel(const float* __restrict__ x, const float* __restrict__ w,
                    float* __restrict__ y) {
    int row = blockIdx.x;
    int tid = threadIdx.x;
    const float* xr = x + (size_t)row * DM;
    float4 v = *(const float4*)(xr + tid * 4);
    float s = v.x * v.x + v.y * v.y + v.z * v.z + v.w * v.w;
    #pragma unroll
    for (int off = 16; off; off >>= 1)
        s += __shfl_xor_sync(0xffffffffu, s, off);
    __shared__ float red[8];
    if ((tid & 31) == 0) red[tid >> 5] = s;
    __syncthreads();
    float tot = red[0] + red[1] + red[2] + red[3] +
                red[4] + red[5] + red[6] + red[7];
    float inv = rsqrtf(tot * (1.0f / DM) + 1e-5f);
    float4 wv = *(const float4*)(w + tid * 4);
    v.x *= inv * wv.x; v.y *= inv * wv.y; v.z *= inv * wv.z; v.w *= inv * wv.w;
    *(float4*)(y + (size_t)row * DM + tid * 4) = v;
}

// ---------------------------------------------------------------------------
// RoPE in-place on q and k.
// ---------------------------------------------------------------------------
__global__ __launch_bounds__(256)
void rope_kernel(float* __restrict__ q, float* __restrict__ k) {
    int idx = blockIdx.x * blockDim.x + threadIdx.x;
    if (idx >= M_ROWS * 512) return;
    int m  = idx >> 9;
    int pir = idx & 511;
    int h  = pir >> 5;
    int pp = pir & 31;
    int s  = m & (SEQ - 1);
    float inv_freq = expf(-(float)(2 * pp) * (9.210340371976184f / 64.0f));
    float ang = (float)s * inv_freq;
    float sn, cs;
    sincosf(ang, &sn, &cs);
    size_t off = (size_t)m * DM + h * HD + 2 * pp;
    float qe = q[off], qo = q[off + 1];
    q[off]     = qe * cs - qo * sn;
    q[off + 1] = qo * cs + qe * sn;
    float ke = k[off], ko = k[off + 1];
    k[off]     = ke * cs - ko * sn;
    k[off + 1] = ko * cs + ke * sn;
}

// ---------------------------------------------------------------------------
// TF32 tensor-core GEMM: C[M,N] = A[M,K] * W[N,K]^T (+epilogue), 3xTF32 split.
// 128x128x32 tile, 256 thr (8 warps, 2x4 warp grid, 64x32 warp tile).
// Smem: XOR-swizzled [row][32] tiles, double-buffered via cp.async. 64KB dyn.
// EPI: 0 none, 1 C=AB+aux, 2 C=silu(AB)*aux
// ---------------------------------------------------------------------------
__device__ __forceinline__ unsigned f2tf(float v) {
    unsigned r;
    asm("cvt.rna.tf32.f32 %0, %1;" : "=r"(r) : "f"(v));
    return r;
}
__device__ __forceinline__ void mma8(float* d, const unsigned* a,
                                     const unsigned* b) {
    asm volatile(
        "mma.sync.aligned.m16n8k8.row.col.f32.tf32.tf32.f32 "
        "{%0,%1,%2,%3}, {%4,%5,%6,%7}, {%8,%9}, {%0,%1,%2,%3};"
        : "+f"(d[0]), "+f"(d[1]), "+f"(d[2]), "+f"(d[3])
        : "r"(a[0]), "r"(a[1]), "r"(a[2]), "r"(a[3]), "r"(b[0]), "r"(b[1]));
}
__device__ __forceinline__ void cp_async16(uint32_t s, const void* g) {
    asm volatile("cp.async.cg.shared.global [%0], [%1], 16;\n"
                 :: "r"(s), "l"(g));
}
__device__ __forceinline__ void cp_commit() {
    asm volatile("cp.async.commit_group;\n");
}
__device__ __forceinline__ void cp_wait0() {
    asm volatile("cp.async.wait_group 0;\n");
}

template <int EPI>
__global__ __launch_bounds__(256, 1)
void tgemm_kernel(const float* __restrict__ A, const float* __restrict__ W,
                  float* __restrict__ C, const float* __restrict__ aux,
                  int N, int K) {
    extern __shared__ float sm[];   // A0 A1 B0 B1, 4096 floats each (64KB)
    int tid = threadIdx.x;
    int wid = tid >> 5, lane = tid & 31;
    int g = lane >> 2, t = lane & 3;
    int wm = wid >> 2, wn = wid & 3;      // 2 x 4 warps
    int m0 = blockIdx.y * 128;
    int n0 = blockIdx.x * 128;

    // gmem->smem mapping: thread covers rows r0+32*i, cols c4..c4+3
    int r0 = tid >> 3;
    int c4 = (tid & 7) << 2;
    uint32_t smem_base = (uint32_t)__cvta_generic_to_shared(sm);

    float acc[4][4][4];
    #pragma unroll
    for (int i = 0; i < 4; ++i)
        #pragma unroll
        for (int j = 0; j < 4; ++j)
            #pragma unroll
            for (int c = 0; c < 4; ++c) acc[i][j][c] = 0.0f;

    int niter = K >> 5;   // K / 32

    // stage(buf, k0): issue 8 cp.async per thread (4 A rows + 4 B rows)
    #define STAGE(buf, k0)                                                     \
    {                                                                          \
        _Pragma("unroll")                                                      \
        for (int i = 0; i < 4; ++i) {                                          \
            int r = r0 + 32 * i;                                               \
            int sw = (c4 ^ ((r & 7) << 2));                                    \
            uint32_t da = smem_base + ((buf)*4096 + r * 32 + sw) * 4;          \
            cp_async16(da, A + (size_t)(m0 + r) * K + (k0) + c4);              \
            uint32_t db = smem_base + (8192 + (buf)*4096 + r * 32 + sw) * 4;   \
            cp_async16(db, W + (size_t)(n0 + r) * K + (k0) + c4);              \
        }                                                                      \
        cp_commit();                                                           \
    }

    STAGE(0, 0);
    cp_wait0();
    __syncthreads();

    int buf = 0;
    for (int it = 0; it < niter; ++it) {
        if (it + 1 < niter) STAGE(buf ^ 1, (it + 1) << 5);

        const float* smA = sm + buf * 4096;
        const float* smB = sm + 8192 + buf * 4096;

        #pragma unroll
        for (int ks = 0; ks < 4; ++ks) {
            int kb = ks << 3;
            unsigned bhi[4][2], blo[4][2];
            #pragma unroll
            for (int nt = 0; nt < 4; ++nt) {
                int n = wn * 32 + nt * 8 + g;
                #pragma unroll
                for (int rr = 0; rr < 2; ++rr) {
                    int k = kb + t + rr * 4;
                    float v = smB[n * 32 + (k ^ ((n & 7) << 2))];
                    bhi[nt][rr] = f2tf(v);
                    blo[nt][rr] = f2tf(v - __uint_as_float(bhi[nt][rr]));
                }
            }
            #pragma unroll
            for (int mt = 0; mt < 4; ++mt) {
                unsigned ahi[4], alo[4];
                #pragma unroll
                for (int i = 0; i < 4; ++i) {
                    int r = wm * 64 + mt * 16 + g + (i & 1) * 8;
                    int k = kb + t + (i >> 1) * 4;
                    float v = smA[r * 32 + (k ^ ((r & 7) << 2))];
                    ahi[i] = f2tf(v);
                    alo[i] = f2tf(v - __uint_as_float(ahi[i]));
                }
                #pragma unroll
                for (int nt = 0; nt < 4; ++nt) {
                    mma8(acc[mt][nt], ahi, bhi[nt]);
                    mma8(acc[mt][nt], alo, bhi[nt]);
                    mma8(acc[mt][nt], ahi, blo[nt]);
                }
            }
        }

        if (it + 1 < niter) cp_wait0();
        __syncthreads();
        buf ^= 1;
    }
    #undef STAGE

    // Epilogue
    #pragma unroll
    for (int mt = 0; mt < 4; ++mt) {
        #pragma unroll
        for (int nt = 0; nt < 4; ++nt) {
            int rb = m0 + wm * 64 + mt * 16 + g;
            int cb = n0 + wn * 32 + nt * 8 + 2 * t;
            #pragma unroll
            for (int half = 0; half < 2; ++half) {
                int row = rb + half * 8;
                size_t off = (size_t)row * N + cb;
                #pragma unroll
                for (int e = 0; e < 2; ++e) {
                    float u = acc[mt][nt][half * 2 + e];
                    float r;
                    if (EPI == 0) {
                        r = u;
                    } else if (EPI == 1) {
                        r = u + aux[off + e];
                    } else {
                        float sg = 1.0f / (1.0f + __expf(-u));
                        r = u * sg * aux[off + e];
                    }
                    C[off + e] = r;
                }
            }
        }
    }
}

// ---------------------------------------------------------------------------
// Flash attention (fp32, causal). Unchanged from round 1.
// ---------------------------------------------------------------------------
__global__ __launch_bounds__(256)
void flash_kernel(const float* __restrict__ q, const float* __restrict__ k,
                  const float* __restrict__ v, float* __restrict__ o) {
    extern __shared__ float sm[];
    float* Qs  = sm;                 // 64*64
    float* KVs = sm + 4096;          // 64*65
    float* Ps  = sm + 4096 + 4160;   // 64*64

    int tid = threadIdx.x;
    int tx = tid & 15, ty = tid >> 4;
    int qb = blockIdx.x;
    int bh = blockIdx.y;
    int b = bh >> 4, h = bh & 15;
    int i0 = qb * 64;
    size_t base = ((size_t)b * SEQ) * DM + h * HD;

    for (int t = tid; t < 1024; t += 256) {
        int r = t >> 4, c4 = (t & 15) << 2;
        *(float4*)(Qs + r * 64 + c4) =
            *(const float4*)(q + base + (size_t)(i0 + r) * DM + c4);
    }

    float acc[4][4];
    float mrow[4], lrow[4];
    #pragma unroll
    for (int i = 0; i < 4; ++i) {
        mrow[i] = -1e30f; lrow[i] = 0.0f;
        #pragma unroll
        for (int j = 0; j < 4; ++j) acc[i][j] = 0.0f;
    }

    for (int j = 0; j <= qb; ++j) {
        __syncthreads();
        for (int t = tid; t < 1024; t += 256) {
            int r = t >> 4, c4 = (t & 15) << 2;
            float4 kv = *(const float4*)(k + base + (size_t)(j * 64 + r) * DM + c4);
            float* d = KVs + r * 65 + c4;
            d[0] = kv.x; d[1] = kv.y; d[2] = kv.z; d[3] = kv.w;
        }
        __syncthreads();

        float sreg[4][4];
        #pragma unroll
        for (int i = 0; i < 4; ++i)
            #pragma unroll
            for (int jj = 0; jj < 4; ++jj) sreg[i][jj] = 0.0f;
        #pragma unroll 16
        for (int d = 0; d < 64; ++d) {
            float a[4], bb[4];
            #pragma unroll
            for (int i = 0; i < 4; ++i)  a[i]  = Qs[(ty * 4 + i) * 64 + d];
            #pragma unroll
            for (int jj = 0; jj < 4; ++jj) bb[jj] = KVs[(tx * 4 + jj) * 65 + d];
            #pragma unroll
            for (int i = 0; i < 4; ++i)
                #pragma unroll
                for (int jj = 0; jj < 4; ++jj)
                    sreg[i][jj] += a[i] * bb[jj];
        }

        bool diag = (j == qb);
        #pragma unroll
        for (int i = 0; i < 4; ++i)
            #pragma unroll
            for (int jj = 0; jj < 4; ++jj) {
                float val = sreg[i][jj] * 0.125f;
                if (diag && (tx * 4 + jj) > (ty * 4 + i)) val = -1e30f;
                sreg[i][jj] = val;
            }

        #pragma unroll
        for (int i = 0; i < 4; ++i) {
            float rmax = fmaxf(fmaxf(sreg[i][0], sreg[i][1]),
                               fmaxf(sreg[i][2], sreg[i][3]));
            #pragma unroll
            for (int off = 8; off; off >>= 1)
                rmax = fmaxf(rmax, __shfl_xor_sync(0xffffffffu, rmax, off, 16));
            float mnew = fmaxf(mrow[i], rmax);
            float corr = __expf(mrow[i] - mnew);
            mrow[i] = mnew;
            float4 p;
            p.x = __expf(sreg[i][0] - mnew);
            p.y = __expf(sreg[i][1] - mnew);
            p.z = __expf(sreg[i][2] - mnew);
            p.w = __expf(sreg[i][3] - mnew);
            float rs = p.x + p.y + p.z + p.w;
            #pragma unroll
            for (int off = 8; off; off >>= 1)
                rs += __shfl_xor_sync(0xffffffffu, rs, off, 16);
            lrow[i] = lrow[i] * corr + rs;
            *(float4*)(Ps + (ty * 4 + i) * 64 + tx * 4) = p;
            #pragma unroll
            for (int jj = 0; jj < 4; ++jj) acc[i][jj] *= corr;
        }
        __syncthreads();

        for (int t = tid; t < 1024; t += 256) {
            int r = t >> 4, c4 = (t & 15) << 2;
            float4 vv = *(const float4*)(v + base + (size_t)(j * 64 + r) * DM + c4);
            float* d = KVs + r * 65 + c4;
            d[0] = vv.x; d[1] = vv.y; d[2] = vv.z; d[3] = vv.w;
        }
        __syncthreads();

        #pragma unroll 16
        for (int c = 0; c < 64; ++c) {
            float p[4], vv[4];
            #pragma unroll
            for (int i = 0; i < 4; ++i)  p[i]  = Ps[(ty * 4 + i) * 64 + c];
            #pragma unroll
            for (int jj = 0; jj < 4; ++jj) vv[jj] = KVs[c * 65 + tx * 4 + jj];
            #pragma unroll
            for (int i = 0; i < 4; ++i)
                #pragma unroll
                for (int jj = 0; jj < 4; ++jj)
                    acc[i][jj] += p[i] * vv[jj];
        }
    }

    #pragma unroll
    for (int i = 0; i < 4; ++i) {
        float inv = 1.0f / lrow[i];
        #pragma unroll
        for (int jj = 0; jj < 4; ++jj)
            o[base + (size_t)(i0 + ty * 4 + i) * DM + tx * 4 + jj] =
                acc[i][jj] * inv;
    }
}

// ---------------------------------------------------------------------------
// Launch
// ---------------------------------------------------------------------------
extern "C" void kernel_launch(void* const* d_in, const int* in_sizes, int n_in,
                              void* d_out, int out_size) {
    const float* x     = (const float*)d_in[0];
    const float* wq    = (const float*)d_in[1];
    const float* wk    = (const float*)d_in[2];
    const float* wv    = (const float*)d_in[3];
    const float* wo    = (const float*)d_in[4];
    const float* ln1w  = (const float*)d_in[5];
    const float* ln2w  = (const float*)d_in[6];
    const float* upw   = (const float*)d_in[7];
    const float* gatew = (const float*)d_in[8];
    const float* downw = (const float*)d_in[9];
    float* out = (float*)d_out;

    float *xn, *q, *k, *v, *ao, *x1, *gate, *hbuf;
    cudaGetSymbolAddress((void**)&xn,   g_xn);
    cudaGetSymbolAddress((void**)&q,    g_q);
    cudaGetSymbolAddress((void**)&k,    g_k);
    cudaGetSymbolAddress((void**)&v,    g_v);
    cudaGetSymbolAddress((void**)&ao,   g_ao);
    cudaGetSymbolAddress((void**)&x1,   g_x1);
    cudaGetSymbolAddress((void**)&gate, g_gate);
    cudaGetSymbolAddress((void**)&hbuf, g_h);

    cudaFuncSetAttribute(flash_kernel,
                         cudaFuncAttributeMaxDynamicSharedMemorySize, 49408);
    cudaFuncSetAttribute(tgemm_kernel<0>,
                         cudaFuncAttributeMaxDynamicSharedMemorySize, 65536);
    cudaFuncSetAttribute(tgemm_kernel<1>,
                         cudaFuncAttributeMaxDynamicSharedMemorySize, 65536);
    cudaFuncSetAttribute(tgemm_kernel<2>,
                         cudaFuncAttributeMaxDynamicSharedMemorySize, 65536);

    dim3 g1(DM / 128, M_ROWS / 128);    // (8, 64)
    dim3 g2(DFF / 128, M_ROWS / 128);   // (32, 64)

    rmsnorm_kernel<<<M_ROWS, 256>>>(x, ln1w, xn);
    tgemm_kernel<0><<<g1, 256, 65536>>>(xn, wq, q, nullptr, DM, DM);
    tgemm_kernel<0><<<g1, 256, 65536>>>(xn, wk, k, nullptr, DM, DM);
    tgemm_kernel<0><<<g1, 256, 65536>>>(xn, wv, v, nullptr, DM, DM);
    rope_kernel<<<(M_ROWS * 512) / 256, 256>>>(q, k);
    flash_kernel<<<dim3(SEQ / 64, B_SZ * NHEAD), 256, 49408>>>(q, k, v, ao);
    tgemm_kernel<1><<<g1, 256, 65536>>>(ao, wo, x1, x, DM, DM);
    rmsnorm_kernel<<<M_ROWS, 256>>>(x1, ln2w, xn);
    tgemm_kernel<0><<<g2, 256, 65536>>>(xn, gatew, gate, nullptr, DFF, DM);
    tgemm_kernel<2><<<g2, 256, 65536>>>(xn, upw, hbuf, gate, DFF, DM);
    tgemm_kernel<1><<<g1, 256, 65536>>>(hbuf, downw, out, x1, DM, DFF);
}

// round 4
// speedup vs baseline: 1.8182x; 1.3626x over previous
#include <cuda_runtime.h>
#include <cuda_bf16.h>
#include <math.h>
#include <stdint.h>

// Problem constants
#define B_SZ 4
#define SEQ 2048
#define DM 1024
#define NHEAD 16
#define HD 64
#define DFF 4096
#define M_ROWS (B_SZ * SEQ)   // 8192

typedef __nv_bfloat16 bf16;

// ---------------------------------------------------------------------------
// Scratch buffers
// ---------------------------------------------------------------------------
__device__ float g_q[M_ROWS * DM];
__device__ float g_k[M_ROWS * DM];
__device__ float g_v[M_ROWS * DM];
__device__ float g_ao[M_ROWS * DM];
__device__ float g_x1[M_ROWS * DM];
__device__ float g_gate[M_ROWS * DFF];

__device__ bf16 g_xnh[M_ROWS * DM],  g_xnl[M_ROWS * DM];
__device__ bf16 g_aoh[M_ROWS * DM],  g_aol[M_ROWS * DM];
__device__ bf16 g_hh[M_ROWS * DFF],  g_hl[M_ROWS * DFF];

__device__ bf16 g_wqh[DM * DM],   g_wql[DM * DM];
__device__ bf16 g_wkh[DM * DM],   g_wkl[DM * DM];
__device__ bf16 g_wvh[DM * DM],   g_wvl[DM * DM];
__device__ bf16 g_woh[DM * DM],   g_wol[DM * DM];
__device__ bf16 g_uph[DFF * DM],  g_upl[DFF * DM];
__device__ bf16 g_gwh[DFF * DM],  g_gwl[DFF * DM];
__device__ bf16 g_dwh[DM * DFF],  g_dwl[DM * DFF];

__device__ __forceinline__ void split1(float r, bf16* hi, bf16* lo, size_t off) {
    bf16 h = __float2bfloat16(r);
    hi[off] = h;
    lo[off] = __float2bfloat16(r - __bfloat162float(h));
}

// ---------------------------------------------------------------------------
// Split fp32 -> (hi, lo) bf16 pair. grid = n/1024, 256 threads x 4 elts.
// ---------------------------------------------------------------------------
__global__ __launch_bounds__(256)
void split_kernel(const float* __restrict__ src, bf16* __restrict__ hi,
                  bf16* __restrict__ lo) {
    size_t i = ((size_t)blockIdx.x * 256 + threadIdx.x) * 4;
    float4 v = *(const float4*)(src + i);
    split1(v.x, hi, lo, i + 0);
    split1(v.y, hi, lo, i + 1);
    split1(v.z, hi, lo, i + 2);
    split1(v.w, hi, lo, i + 3);
}

// ---------------------------------------------------------------------------
// RMSNorm with split output: one block per row of 1024, 256 thr x 4
// ---------------------------------------------------------------------------
__global__ __launch_bounds__(256)
void rmsnorm_split_kernel(const float* __restrict__ x,
                          const float* __restrict__ w,
                          bf16* __restrict__ hi, bf16* __restrict__ lo) {
    int row = blockIdx.x;
    int tid = threadIdx.x;
    const float* xr = x + (size_t)row * DM;
    float4 v = *(const float4*)(xr + tid * 4);
    float s = v.x * v.x + v.y * v.y + v.z * v.z + v.w * v.w;
    #pragma unroll
    for (int off = 16; off; off >>= 1)
        s += __shfl_xor_sync(0xffffffffu, s, off);
    __shared__ float red[8];
    if ((tid & 31) == 0) red[tid >> 5] = s;
    __syncthreads();
    float tot = red[0] + red[1] + red[2] + red[3] +
                red[4] + red[5] + red[6] + red[7];
    float inv = rsqrtf(tot * (1.0f / DM) + 1e-5f);
    float4 wv = *(const float4*)(w + tid * 4);
    size_t o = (size_t)row * DM + tid * 4;
    split1(v.x * inv * wv.x, hi, lo, o + 0);
    split1(v.y * inv * wv.y, hi, lo, o + 1);
    split1(v.z * inv * wv.z, hi, lo, o + 2);
    split1(v.w * inv * wv.w, hi, lo, o + 3);
}

// ---------------------------------------------------------------------------
// RoPE in-place on q and k.
// ---------------------------------------------------------------------------
__global__ __launch_bounds__(256)
void rope_kernel(float* __restrict__ q, float* __restrict__ k) {
    int idx = blockIdx.x * blockDim.x + threadIdx.x;
    if (idx >= M_ROWS * 512) return;
    int m  = idx >> 9;
    int pir = idx & 511;
    int h  = pir >> 5;
    int pp = pir & 31;
    int s  = m & (SEQ - 1);
    float inv_freq = expf(-(float)(2 * pp) * (9.210340371976184f / 64.0f));
    float ang = (float)s * inv_freq;
    float sn, cs;
    sincosf(ang, &sn, &cs);
    size_t off = (size_t)m * DM + h * HD + 2 * pp;
    float qe = q[off], qo = q[off + 1];
    q[off]     = qe * cs - qo * sn;
    q[off + 1] = qo * cs + qe * sn;
    float ke = k[off], ko = k[off + 1];
    k[off]     = ke * cs - ko * sn;
    k[off + 1] = ko * cs + ke * sn;
}

// ---------------------------------------------------------------------------
// bf16 split-compensated tensor GEMM: C[M,N] = A[M,K] * W[N,K]^T (+epilogue)
// A, W given as (hi, lo) bf16 pairs; D += Ah*Wh + Al*Wh + Ah*Wl.
// 128x128x32 tile, 256 thr (8 warps 2x4, 64x32 warp tile), mma.m16n8k16.
// Smem per stage: Ah/Al/Bh/Bl 8KB each = 32KB; double buffered = 64KB.
// Row layout: 32 bf16 = 4 chunks of 16B, chunk' = chunk ^ ((row>>1)&3).
// EPI: 0 C=AB; 1 C=AB+aux; 2 (Ch,Cl)=split(silu(AB)*aux)
// ---------------------------------------------------------------------------
__device__ __forceinline__ void mma16(float* d, const unsigned* a,
                                      const unsigned* b) {
    asm volatile(
        "mma.sync.aligned.m16n8k16.row.col.f32.bf16.bf16.f32 "
        "{%0,%1,%2,%3}, {%4,%5,%6,%7}, {%8,%9}, {%0,%1,%2,%3};"
        : "+f"(d[0]), "+f"(d[1]), "+f"(d[2]), "+f"(d[3])
        : "r"(a[0]), "r"(a[1]), "r"(a[2]), "r"(a[3]), "r"(b[0]), "r"(b[1]));
}
__device__ __forceinline__ void cp_async16(uint32_t s, const void* g) {
    asm volatile("cp.async.cg.shared.global [%0], [%1], 16;\n"
                 :: "r"(s), "l"(g));
}
__device__ __forceinline__ void cp_commit() {
    asm volatile("cp.async.commit_group;\n");
}
__device__ __forceinline__ void cp_wait0() {
    asm volatile("cp.async.wait_group 0;\n");
}
// smem fragment word: row stride 64B, swizzled 16B chunks
__device__ __forceinline__ unsigned lds_frag(const char* tile, int row, int kw) {
    return *(const unsigned*)(tile + row * 64 +
                              ((((kw >> 2) ^ ((row >> 1) & 3))) << 4) +
                              ((kw & 3) << 2));
}

template <int EPI>
__global__ __launch_bounds__(256, 1)
void bgemm_kernel(const bf16* __restrict__ Ah, const bf16* __restrict__ Al,
                  const bf16* __restrict__ Wh, const bf16* __restrict__ Wl,
                  float* __restrict__ C, bf16* __restrict__ Ch,
                  bf16* __restrict__ Cl, const float* __restrict__ aux,
                  int N, int K) {
    extern __shared__ char smc[];   // [2 stages][Ah Al Bh Bl][8KB]
    int tid = threadIdx.x;
    int wid = tid >> 5, lane = tid & 31;
    int g = lane >> 2, t = lane & 3;
    int wm = wid >> 2, wn = wid & 3;      // 2 x 4 warps
    int m0 = blockIdx.y * 128;
    int n0 = blockIdx.x * 128;

    uint32_t smem_base = (uint32_t)__cvta_generic_to_shared(smc);

    float acc[4][4][4];
    #pragma unroll
    for (int i = 0; i < 4; ++i)
        #pragma unroll
        for (int j = 0; j < 4; ++j)
            #pragma unroll
            for (int c = 0; c < 4; ++c) acc[i][j][c] = 0.0f;

    int niter = K >> 5;   // K / 32

    // per-thread gmem->smem mapping: row = tid>>1, two 16B chunks
    int grow = tid >> 1;
    int gch0 = (tid & 1) << 1;

    #define STAGE(buf, k0)                                                      \
    {                                                                           \
        _Pragma("unroll")                                                       \
        for (int cc = 0; cc < 2; ++cc) {                                        \
            int ch = gch0 + cc;                                                 \
            uint32_t soff = (uint32_t)(grow * 64 +                              \
                ((ch ^ ((grow >> 1) & 3)) << 4));                               \
            size_t ga = (size_t)(m0 + grow) * K + (k0) + ch * 8;                \
            size_t gb = (size_t)(n0 + grow) * K + (k0) + ch * 8;                \
            uint32_t sb = smem_base + (buf) * 32768 + soff;                     \
            cp_async16(sb,         Ah + ga);                                    \
            cp_async16(sb + 8192,  Al + ga);                                    \
            cp_async16(sb + 16384, Wh + gb);                                    \
            cp_async16(sb + 24576, Wl + gb);                                    \
        }                                                                       \
        cp_commit();                                                            \
    }

    STAGE(0, 0);
    cp_wait0();
    __syncthreads();

    int buf = 0;
    for (int it = 0; it < niter; ++it) {
        if (it + 1 < niter) STAGE(buf ^ 1, (it + 1) << 5);

        const char* tAh = smc + buf * 32768;
        const char* tAl = tAh + 8192;
        const char* tBh = tAh + 16384;
        const char* tBl = tAh + 24576;

        #pragma unroll
        for (int ck = 0; ck < 2; ++ck) {
            int kw0 = ck * 8 + t;
            unsigned bh[4][2], bl[4][2];
            #pragma unroll
            for (int nt = 0; nt < 4; ++nt) {
                int n = wn * 32 + nt * 8 + g;
                bh[nt][0] = lds_frag(tBh, n, kw0);
                bh[nt][1] = lds_frag(tBh, n, kw0 + 4);
                bl[nt][0] = lds_frag(tBl, n, kw0);
                bl[nt][1] = lds_frag(tBl, n, kw0 + 4);
            }
            #pragma unroll
            for (int mt = 0; mt < 4; ++mt) {
                int r = wm * 64 + mt * 16 + g;
                unsigned ah[4], al[4];
                ah[0] = lds_frag(tAh, r,     kw0);
                ah[1] = lds_frag(tAh, r + 8, kw0);
                ah[2] = lds_frag(tAh, r,     kw0 + 4);
                ah[3] = lds_frag(tAh, r + 8, kw0 + 4);
                al[0] = lds_frag(tAl, r,     kw0);
                al[1] = lds_frag(tAl, r + 8, kw0);
                al[2] = lds_frag(tAl, r,     kw0 + 4);
                al[3] = lds_frag(tAl, r + 8, kw0 + 4);
                #pragma unroll
                for (int nt = 0; nt < 4; ++nt) {
                    mma16(acc[mt][nt], ah, bh[nt]);
                    mma16(acc[mt][nt], al, bh[nt]);
                    mma16(acc[mt][nt], ah, bl[nt]);
                }
            }
        }

        if (it + 1 < niter) cp_wait0();
        __syncthreads();
        buf ^= 1;
    }
    #undef STAGE

    // Epilogue. acc regs: c0,c1 -> (row rb, col cb+0/1); c2,c3 -> (rb+8, cb+0/1)
    #pragma unroll
    for (int mt = 0; mt < 4; ++mt) {
        #pragma unroll
        for (int nt = 0; nt < 4; ++nt) {
            int rb = m0 + wm * 64 + mt * 16 + g;
            int cb = n0 + wn * 32 + nt * 8 + 2 * t;
            #pragma unroll
            for (int half = 0; half < 2; ++half) {
                size_t off = (size_t)(rb + half * 8) * N + cb;
                #pragma unroll
                for (int e = 0; e < 2; ++e) {
                    float u = acc[mt][nt][half * 2 + e];
                    if (EPI == 0) {
                        C[off + e] = u;
                    } else if (EPI == 1) {
                        C[off + e] = u + aux[off + e];
                    } else {
                        float sg = 1.0f / (1.0f + __expf(-u));
                        float r = u * sg * aux[off + e];
                        split1(r, Ch, Cl, off + e);
                    }
                }
            }
        }
    }
}

// ---------------------------------------------------------------------------
// Flash attention (fp32, causal). Unchanged.
// ---------------------------------------------------------------------------
__global__ __launch_bounds__(256)
void flash_kernel(const float* __restrict__ q, const float* __restrict__ k,
                  const float* __restrict__ v, float* __restrict__ o) {
    extern __shared__ float sm[];
    float* Qs  = sm;                 // 64*64
    float* KVs = sm + 4096;          // 64*65
    float* Ps  = sm + 4096 + 4160;   // 64*64

    int tid = threadIdx.x;
    int tx = tid & 15, ty = tid >> 4;
    int qb = blockIdx.x;
    int bh = blockIdx.y;
    int b = bh >> 4, h = bh & 15;
    int i0 = qb * 64;
    size_t base = ((size_t)b * SEQ) * DM + h * HD;

    for (int t = tid; t < 1024; t += 256) {
        int r = t >> 4, c4 = (t & 15) << 2;
        *(float4*)(Qs + r * 64 + c4) =
            *(const float4*)(q + base + (size_t)(i0 + r) * DM + c4);
    }

    float acc[4][4];
    float mrow[4], lrow[4];
    #pragma unroll
    for (int i = 0; i < 4; ++i) {
        mrow[i] = -1e30f; lrow[i] = 0.0f;
        #pragma unroll
        for (int j = 0; j < 4; ++j) acc[i][j] = 0.0f;
    }

    for (int j = 0; j <= qb; ++j) {
        __syncthreads();
        for (int t = tid; t < 1024; t += 256) {
            int r = t >> 4, c4 = (t & 15) << 2;
            float4 kv = *(const float4*)(k + base + (size_t)(j * 64 + r) * DM + c4);
            float* d = KVs + r * 65 + c4;
            d[0] = kv.x; d[1] = kv.y; d[2] = kv.z; d[3] = kv.w;
        }
        __syncthreads();

        float sreg[4][4];
        #pragma unroll
        for (int i = 0; i < 4; ++i)
            #pragma unroll
            for (int jj = 0; jj < 4; ++jj) sreg[i][jj] = 0.0f;
        #pragma unroll 16
        for (int d = 0; d < 64; ++d) {
            float a[4], bb[4];
            #pragma unroll
            for (int i = 0; i < 4; ++i)  a[i]  = Qs[(ty * 4 + i) * 64 + d];
            #pragma unroll
            for (int jj = 0; jj < 4; ++jj) bb[jj] = KVs[(tx * 4 + jj) * 65 + d];
            #pragma unroll
            for (int i = 0; i < 4; ++i)
                #pragma unroll
                for (int jj = 0; jj < 4; ++jj)
                    sreg[i][jj] += a[i] * bb[jj];
        }

        bool diag = (j == qb);
        #pragma unroll
        for (int i = 0; i < 4; ++i)
            #pragma unroll
            for (int jj = 0; jj < 4; ++jj) {
                float val = sreg[i][jj] * 0.125f;
                if (diag && (tx * 4 + jj) > (ty * 4 + i)) val = -1e30f;
                sreg[i][jj] = val;
            }

        #pragma unroll
        for (int i = 0; i < 4; ++i) {
            float rmax = fmaxf(fmaxf(sreg[i][0], sreg[i][1]),
                               fmaxf(sreg[i][2], sreg[i][3]));
            #pragma unroll
            for (int off = 8; off; off >>= 1)
                rmax = fmaxf(rmax, __shfl_xor_sync(0xffffffffu, rmax, off, 16));
            float mnew = fmaxf(mrow[i], rmax);
            float corr = __expf(mrow[i] - mnew);
            mrow[i] = mnew;
            float4 p;
            p.x = __expf(sreg[i][0] - mnew);
            p.y = __expf(sreg[i][1] - mnew);
            p.z = __expf(sreg[i][2] - mnew);
            p.w = __expf(sreg[i][3] - mnew);
            float rs = p.x + p.y + p.z + p.w;
            #pragma unroll
            for (int off = 8; off; off >>= 1)
                rs += __shfl_xor_sync(0xffffffffu, rs, off, 16);
            lrow[i] = lrow[i] * corr + rs;
            *(float4*)(Ps + (ty * 4 + i) * 64 + tx * 4) = p;
            #pragma unroll
            for (int jj = 0; jj < 4; ++jj) acc[i][jj] *= corr;
        }
        __syncthreads();

        for (int t = tid; t < 1024; t += 256) {
            int r = t >> 4, c4 = (t & 15) << 2;
            float4 vv = *(const float4*)(v + base + (size_t)(j * 64 + r) * DM + c4);
            float* d = KVs + r * 65 + c4;
            d[0] = vv.x; d[1] = vv.y; d[2] = vv.z; d[3] = vv.w;
        }
        __syncthreads();

        #pragma unroll 16
        for (int c = 0; c < 64; ++c) {
            float p[4], vv[4];
            #pragma unroll
            for (int i = 0; i < 4; ++i)  p[i]  = Ps[(ty * 4 + i) * 64 + c];
            #pragma unroll
            for (int jj = 0; jj < 4; ++jj) vv[jj] = KVs[c * 65 + tx * 4 + jj];
            #pragma unroll
            for (int i = 0; i < 4; ++i)
                #pragma unroll
                for (int jj = 0; jj < 4; ++jj)
                    acc[i][jj] += p[i] * vv[jj];
        }
    }

    #pragma unroll
    for (int i = 0; i < 4; ++i) {
        float inv = 1.0f / lrow[i];
        #pragma unroll
        for (int jj = 0; jj < 4; ++jj)
            o[base + (size_t)(i0 + ty * 4 + i) * DM + tx * 4 + jj] =
                acc[i][jj] * inv;
    }
}

// ---------------------------------------------------------------------------
// Launch
// ---------------------------------------------------------------------------
extern "C" void kernel_launch(void* const* d_in, const int* in_sizes, int n_in,
                              void* d_out, int out_size) {
    const float* x     = (const float*)d_in[0];
    const float* wq    = (const float*)d_in[1];
    const float* wk    = (const float*)d_in[2];
    const float* wv    = (const float*)d_in[3];
    const float* wo    = (const float*)d_in[4];
    const float* ln1w  = (const float*)d_in[5];
    const float* ln2w  = (const float*)d_in[6];
    const float* upw   = (const float*)d_in[7];
    const float* gatew = (const float*)d_in[8];
    const float* downw = (const float*)d_in[9];
    float* out = (float*)d_out;

    float *q, *k, *v, *ao, *x1, *gate;
    cudaGetSymbolAddress((void**)&q,    g_q);
    cudaGetSymbolAddress((void**)&k,    g_k);
    cudaGetSymbolAddress((void**)&v,    g_v);
    cudaGetSymbolAddress((void**)&ao,   g_ao);
    cudaGetSymbolAddress((void**)&x1,   g_x1);
    cudaGetSymbolAddress((void**)&gate, g_gate);

    bf16 *xnh, *xnl, *aoh, *aol, *hh, *hl;
    bf16 *wqh, *wql, *wkh, *wkl, *wvh, *wvl, *woh, *wol;
    bf16 *uph, *upl, *gwh, *gwl, *dwh, *dwl;
    cudaGetSymbolAddress((void**)&xnh, g_xnh);
    cudaGetSymbolAddress((void**)&xnl, g_xnl);
    cudaGetSymbolAddress((void**)&aoh, g_aoh);
    cudaGetSymbolAddress((void**)&aol, g_aol);
    cudaGetSymbolAddress((void**)&hh,  g_hh);
    cudaGetSymbolAddress((void**)&hl,  g_hl);
    cudaGetSymbolAddress((void**)&wqh, g_wqh);
    cudaGetSymbolAddress((void**)&wql, g_wql);
    cudaGetSymbolAddress((void**)&wkh, g_wkh);
    cudaGetSymbolAddress((void**)&wkl, g_wkl);
    cudaGetSymbolAddress((void**)&wvh, g_wvh);
    cudaGetSymbolAddress((void**)&wvl, g_wvl);
    cudaGetSymbolAddress((void**)&woh, g_woh);
    cudaGetSymbolAddress((void**)&wol, g_wol);
    cudaGetSymbolAddress((void**)&uph, g_uph);
    cudaGetSymbolAddress((void**)&upl, g_upl);
    cudaGetSymbolAddress((void**)&gwh, g_gwh);
    cudaGetSymbolAddress((void**)&gwl, g_gwl);
    cudaGetSymbolAddress((void**)&dwh, g_dwh);
    cudaGetSymbolAddress((void**)&dwl, g_dwl);

    cudaFuncSetAttribute(flash_kernel,
                         cudaFuncAttributeMaxDynamicSharedMemorySize, 49408);
    cudaFuncSetAttribute(bgemm_kernel<0>,
                         cudaFuncAttributeMaxDynamicSharedMemorySize, 65536);
    cudaFuncSetAttribute(bgemm_kernel<1>,
                         cudaFuncAttributeMaxDynamicSharedMemorySize, 65536);
    cudaFuncSetAttribute(bgemm_kernel<2>,
                         cudaFuncAttributeMaxDynamicSharedMemorySize, 65536);

    dim3 g1(DM / 128, M_ROWS / 128);    // (8, 64)
    dim3 g2(DFF / 128, M_ROWS / 128);   // (32, 64)

    // Weight splits (cheap, bandwidth-bound)
    split_kernel<<<DM * DM / 1024, 256>>>(wq, wqh, wql);
    split_kernel<<<DM * DM / 1024, 256>>>(wk, wkh, wkl);
    split_kernel<<<DM * DM / 1024, 256>>>(wv, wvh, wvl);
    split_kernel<<<DM * DM / 1024, 256>>>(wo, woh, wol);
    split_kernel<<<DFF * DM / 1024, 256>>>(upw, uph, upl);
    split_kernel<<<DFF * DM / 1024, 256>>>(gatew, gwh, gwl);
    split_kernel<<<DM * DFF / 1024, 256>>>(downw, dwh, dwl);

    // ln1 -> split xn
    rmsnorm_split_kernel<<<M_ROWS, 256>>>(x, ln1w, xnh, xnl);
    // q, k, v projections
    bgemm_kernel<0><<<g1, 256, 65536>>>(xnh, xnl, wqh, wql, q, nullptr, nullptr, nullptr, DM, DM);
    bgemm_kernel<0><<<g1, 256, 65536>>>(xnh, xnl, wkh, wkl, k, nullptr, nullptr, nullptr, DM, DM);
    bgemm_kernel<0><<<g1, 256, 65536>>>(xnh, xnl, wvh, wvl, v, nullptr, nullptr, nullptr, DM, DM);
    rope_kernel<<<(M_ROWS * 512) / 256, 256>>>(q, k);
    flash_kernel<<<dim3(SEQ / 64, B_SZ * NHEAD), 256, 49408>>>(q, k, v, ao);
    // o projection + residual
    split_kernel<<<M_ROWS * DM / 1024, 256>>>(ao, aoh, aol);
    bgemm_kernel<1><<<g1, 256, 65536>>>(aoh, aol, woh, wol, x1, nullptr, nullptr, x, DM, DM);
    // ln2 -> split
    rmsnorm_split_kernel<<<M_ROWS, 256>>>(x1, ln2w, xnh, xnl);
    // FFN
    bgemm_kernel<0><<<g2, 256, 65536>>>(xnh, xnl, gwh, gwl, gate, nullptr, nullptr, nullptr, DFF, DM);
    bgemm_kernel<2><<<g2, 256, 65536>>>(xnh, xnl, uph, upl, nullptr, hh, hl, gate, DFF, DM);
    bgemm_kernel<1><<<g1, 256, 65536>>>(hh, hl, dwh, dwl, out, nullptr, nullptr, x1, DM, DFF);
}

// round 7
// speedup vs baseline: 2.1697x; 1.1934x over previous
#include <cuda_runtime.h>
#include <cuda_bf16.h>
#include <math.h>
#include <stdint.h>

// Problem constants
#define B_SZ 4
#define SEQ 2048
#define DM 1024
#define NHEAD 16
#define HD 64
#define DFF 4096
#define M_ROWS (B_SZ * SEQ)   // 8192

typedef __nv_bfloat16 bf16;

// ---------------------------------------------------------------------------
// Scratch buffers
// ---------------------------------------------------------------------------
__device__ float g_q[M_ROWS * DM];
__device__ float g_k[M_ROWS * DM];
__device__ float g_v[M_ROWS * DM];
__device__ float g_x1[M_ROWS * DM];
__device__ float g_gate[M_ROWS * DFF];

__device__ bf16 g_xnh[M_ROWS * DM],  g_xnl[M_ROWS * DM];
__device__ bf16 g_aoh[M_ROWS * DM],  g_aol[M_ROWS * DM];
__device__ bf16 g_hh[M_ROWS * DFF],  g_hl[M_ROWS * DFF];

__device__ bf16 g_wqh[DM * DM],   g_wql[DM * DM];
__device__ bf16 g_wkh[DM * DM],   g_wkl[DM * DM];
__device__ bf16 g_wvh[DM * DM],   g_wvl[DM * DM];
__device__ bf16 g_woh[DM * DM],   g_wol[DM * DM];
__device__ bf16 g_uph[DFF * DM],  g_upl[DFF * DM];
__device__ bf16 g_gwh[DFF * DM],  g_gwl[DFF * DM];
__device__ bf16 g_dwh[DM * DFF],  g_dwl[DM * DFF];

__device__ __forceinline__ void split1(float r, bf16* hi, bf16* lo, size_t off) {
    bf16 h = __float2bfloat16(r);
    hi[off] = h;
    lo[off] = __float2bfloat16(r - __bfloat162float(h));
}

// pack two floats into a bf16x2 word pair (hi word) + residual (lo word)
__device__ __forceinline__ void split_pack(float f0, float f1,
                                           unsigned& h, unsigned& l) {
    bf16 h0 = __float2bfloat16(f0), h1 = __float2bfloat16(f1);
    unsigned short u0 = *(unsigned short*)&h0, u1 = *(unsigned short*)&h1;
    h = ((unsigned)u1 << 16) | u0;
    bf16 l0 = __float2bfloat16(f0 - __bfloat162float(h0));
    bf16 l1 = __float2bfloat16(f1 - __bfloat162float(h1));
    unsigned short v0 = *(unsigned short*)&l0, v1 = *(unsigned short*)&l1;
    l = ((unsigned)v1 << 16) | v0;
}

// ---------------------------------------------------------------------------
// Split fp32 -> (hi, lo) bf16 pair.
// ---------------------------------------------------------------------------
__global__ __launch_bounds__(256)
void split_kernel(const float* __restrict__ src, bf16* __restrict__ hi,
                  bf16* __restrict__ lo) {
    size_t i = ((size_t)blockIdx.x * 256 + threadIdx.x) * 4;
    float4 v = *(const float4*)(src + i);
    split1(v.x, hi, lo, i + 0);
    split1(v.y, hi, lo, i + 1);
    split1(v.z, hi, lo, i + 2);
    split1(v.w, hi, lo, i + 3);
}

// ---------------------------------------------------------------------------
// RMSNorm with split output
// ---------------------------------------------------------------------------
__global__ __launch_bounds__(256)
void rmsnorm_split_kernel(const float* __restrict__ x,
                          const float* __restrict__ w,
                          bf16* __restrict__ hi, bf16* __restrict__ lo) {
    int row = blockIdx.x;
    int tid = threadIdx.x;
    const float* xr = x + (size_t)row * DM;
    float4 v = *(const float4*)(xr + tid * 4);
    float s = v.x * v.x + v.y * v.y + v.z * v.z + v.w * v.w;
    #pragma unroll
    for (int off = 16; off; off >>= 1)
        s += __shfl_xor_sync(0xffffffffu, s, off);
    __shared__ float red[8];
    if ((tid & 31) == 0) red[tid >> 5] = s;
    __syncthreads();
    float tot = red[0] + red[1] + red[2] + red[3] +
                red[4] + red[5] + red[6] + red[7];
    float inv = rsqrtf(tot * (1.0f / DM) + 1e-5f);
    float4 wv = *(const float4*)(w + tid * 4);
    size_t o = (size_t)row * DM + tid * 4;
    split1(v.x * inv * wv.x, hi, lo, o + 0);
    split1(v.y * inv * wv.y, hi, lo, o + 1);
    split1(v.z * inv * wv.z, hi, lo, o + 2);
    split1(v.w * inv * wv.w, hi, lo, o + 3);
}

// ---------------------------------------------------------------------------
// RoPE in-place on q and k (fp32).
// ---------------------------------------------------------------------------
__global__ __launch_bounds__(256)
void rope_kernel(float* __restrict__ q, float* __restrict__ k) {
    int idx = blockIdx.x * blockDim.x + threadIdx.x;
    if (idx >= M_ROWS * 512) return;
    int m  = idx >> 9;
    int pir = idx & 511;
    int h  = pir >> 5;
    int pp = pir & 31;
    int s  = m & (SEQ - 1);
    float inv_freq = expf(-(float)(2 * pp) * (9.210340371976184f / 64.0f));
    float ang = (float)s * inv_freq;
    float sn, cs;
    sincosf(ang, &sn, &cs);
    size_t off = (size_t)m * DM + h * HD + 2 * pp;
    float qe = q[off], qo = q[off + 1];
    q[off]     = qe * cs - qo * sn;
    q[off + 1] = qo * cs + qe * sn;
    float ke = k[off], ko = k[off + 1];
    k[off]     = ke * cs - ko * sn;
    k[off + 1] = ko * cs + ke * sn;
}

// ---------------------------------------------------------------------------
// mma / ldmatrix / cp.async primitives
// ---------------------------------------------------------------------------
__device__ __forceinline__ void mma16(float* d, const unsigned* a,
                                      const unsigned* b) {
    asm volatile(
        "mma.sync.aligned.m16n8k16.row.col.f32.bf16.bf16.f32 "
        "{%0,%1,%2,%3}, {%4,%5,%6,%7}, {%8,%9}, {%0,%1,%2,%3};"
        : "+f"(d[0]), "+f"(d[1]), "+f"(d[2]), "+f"(d[3])
        : "r"(a[0]), "r"(a[1]), "r"(a[2]), "r"(a[3]), "r"(b[0]), "r"(b[1]));
}
__device__ __forceinline__ void ldmx4(unsigned* r, uint32_t addr) {
    asm volatile(
        "ldmatrix.sync.aligned.m8n8.x4.shared.b16 {%0,%1,%2,%3}, [%4];"
        : "=r"(r[0]), "=r"(r[1]), "=r"(r[2]), "=r"(r[3]) : "r"(addr));
}
__device__ __forceinline__ void ldmx4t(unsigned* r, uint32_t addr) {
    asm volatile(
        "ldmatrix.sync.aligned.m8n8.x4.trans.shared.b16 {%0,%1,%2,%3}, [%4];"
        : "=r"(r[0]), "=r"(r[1]), "=r"(r[2]), "=r"(r[3]) : "r"(addr));
}
__device__ __forceinline__ void cp_async16(uint32_t s, const void* g) {
    asm volatile("cp.async.cg.shared.global [%0], [%1], 16;\n"
                 :: "r"(s), "l"(g));
}
__device__ __forceinline__ void cp_commit() {
    asm volatile("cp.async.commit_group;\n");
}
__device__ __forceinline__ void cp_wait0() {
    asm volatile("cp.async.wait_group 0;\n");
}

// ---------------------------------------------------------------------------
// bf16 split-compensated GEMM (unchanged from round 4)
// ---------------------------------------------------------------------------
__device__ __forceinline__ unsigned lds_frag(const char* tile, int row, int kw) {
    return *(const unsigned*)(tile + row * 64 +
                              ((((kw >> 2) ^ ((row >> 1) & 3))) << 4) +
                              ((kw & 3) << 2));
}

template <int EPI>
__global__ __launch_bounds__(256, 1)
void bgemm_kernel(const bf16* __restrict__ Ah, const bf16* __restrict__ Al,
                  const bf16* __restrict__ Wh, const bf16* __restrict__ Wl,
                  float* __restrict__ C, bf16* __restrict__ Ch,
                  bf16* __restrict__ Cl, const float* __restrict__ aux,
                  int N, int K) {
    extern __shared__ char smc[];
    int tid = threadIdx.x;
    int wid = tid >> 5, lane = tid & 31;
    int g = lane >> 2, t = lane & 3;
    int wm = wid >> 2, wn = wid & 3;
    int m0 = blockIdx.y * 128;
    int n0 = blockIdx.x * 128;

    uint32_t smem_base = (uint32_t)__cvta_generic_to_shared(smc);

    float acc[4][4][4];
    #pragma unroll
    for (int i = 0; i < 4; ++i)
        #pragma unroll
        for (int j = 0; j < 4; ++j)
            #pragma unroll
            for (int c = 0; c < 4; ++c) acc[i][j][c] = 0.0f;

    int niter = K >> 5;
    int grow = tid >> 1;
    int gch0 = (tid & 1) << 1;

    #define STAGE(buf, k0)                                                      \
    {                                                                           \
        _Pragma("unroll")                                                       \
        for (int cc = 0; cc < 2; ++cc) {                                        \
            int ch = gch0 + cc;                                                 \
            uint32_t soff = (uint32_t)(grow * 64 +                              \
                ((ch ^ ((grow >> 1) & 3)) << 4));                               \
            size_t ga = (size_t)(m0 + grow) * K + (k0) + ch * 8;                \
            size_t gb = (size_t)(n0 + grow) * K + (k0) + ch * 8;                \
            uint32_t sb = smem_base + (buf) * 32768 + soff;                     \
            cp_async16(sb,         Ah + ga);                                    \
            cp_async16(sb + 8192,  Al + ga);                                    \
            cp_async16(sb + 16384, Wh + gb);                                    \
            cp_async16(sb + 24576, Wl + gb);                                    \
        }                                                                       \
        cp_commit();                                                            \
    }

    STAGE(0, 0);
    cp_wait0();
    __syncthreads();

    int buf = 0;
    for (int it = 0; it < niter; ++it) {
        if (it + 1 < niter) STAGE(buf ^ 1, (it + 1) << 5);

        const char* tAh = smc + buf * 32768;
        const char* tAl = tAh + 8192;
        const char* tBh = tAh + 16384;
        const char* tBl = tAh + 24576;

        #pragma unroll
        for (int ck = 0; ck < 2; ++ck) {
            int kw0 = ck * 8 + t;
            unsigned bh[4][2], bl[4][2];
            #pragma unroll
            for (int nt = 0; nt < 4; ++nt) {
                int n = wn * 32 + nt * 8 + g;
                bh[nt][0] = lds_frag(tBh, n, kw0);
                bh[nt][1] = lds_frag(tBh, n, kw0 + 4);
                bl[nt][0] = lds_frag(tBl, n, kw0);
                bl[nt][1] = lds_frag(tBl, n, kw0 + 4);
            }
            #pragma unroll
            for (int mt = 0; mt < 4; ++mt) {
                int r = wm * 64 + mt * 16 + g;
                unsigned ah[4], al[4];
                ah[0] = lds_frag(tAh, r,     kw0);
                ah[1] = lds_frag(tAh, r + 8, kw0);
                ah[2] = lds_frag(tAh, r,     kw0 + 4);
                ah[3] = lds_frag(tAh, r + 8, kw0 + 4);
                al[0] = lds_frag(tAl, r,     kw0);
                al[1] = lds_frag(tAl, r + 8, kw0);
                al[2] = lds_frag(tAl, r,     kw0 + 4);
                al[3] = lds_frag(tAl, r + 8, kw0 + 4);
                #pragma unroll
                for (int nt = 0; nt < 4; ++nt) {
                    mma16(acc[mt][nt], ah, bh[nt]);
                    mma16(acc[mt][nt], al, bh[nt]);
                    mma16(acc[mt][nt], ah, bl[nt]);
                }
            }
        }

        if (it + 1 < niter) cp_wait0();
        __syncthreads();
        buf ^= 1;
    }
    #undef STAGE

    #pragma unroll
    for (int mt = 0; mt < 4; ++mt) {
        #pragma unroll
        for (int nt = 0; nt < 4; ++nt) {
            int rb = m0 + wm * 64 + mt * 16 + g;
            int cb = n0 + wn * 32 + nt * 8 + 2 * t;
            #pragma unroll
            for (int half = 0; half < 2; ++half) {
                size_t off = (size_t)(rb + half * 8) * N + cb;
                #pragma unroll
                for (int e = 0; e < 2; ++e) {
                    float u = acc[mt][nt][half * 2 + e];
                    if (EPI == 0) {
                        C[off + e] = u;
                    } else if (EPI == 1) {
                        C[off + e] = u + aux[off + e];
                    } else {
                        float sg = 1.0f / (1.0f + __expf(-u));
                        float r = u * sg * aux[off + e];
                        split1(r, Ch, Cl, off + e);
                    }
                }
            }
        }
    }
}

// ---------------------------------------------------------------------------
// Tensor-core flash attention (causal), bf16 split-compensated.
// Block: 128 q-rows of one (b,h). 256 thr = 8 warps, warp w -> rows 16w..16w+15.
// Key tiles of 64. smem (bf16, 128B rows, chunk^(row&7) swizzle):
//   Qh 0, Ql 16K, Kh 32K, Kl 40K, Vh 48K, Vl 56K  = 64KB
// Writes ao directly as (hi,lo) bf16 split.
// ---------------------------------------------------------------------------
__global__ __launch_bounds__(256, 1)
void flash_kernel(const float* __restrict__ q, const float* __restrict__ k,
                  const float* __restrict__ v,
                  bf16* __restrict__ aoh, bf16* __restrict__ aol) {
    extern __shared__ char sm[];
    char* Qh = sm;
    char* Ql = sm + 16384;
    char* Kh = sm + 32768;
    char* Kl = sm + 40960;
    char* Vh = sm + 49152;
    char* Vl = sm + 57344;
    uint32_t uQh = (uint32_t)__cvta_generic_to_shared(Qh);
    uint32_t uQl = uQh + 16384;
    uint32_t uKh = uQh + 32768;
    uint32_t uKl = uQh + 40960;
    uint32_t uVh = uQh + 49152;
    uint32_t uVl = uQh + 57344;

    int tid = threadIdx.x;
    int wid = tid >> 5, lane = tid & 31;
    int g = lane >> 2, t = lane & 3;
    int qb = blockIdx.x;
    int bh = blockIdx.y;
    int b = bh >> 4, h = bh & 15;
    int i0 = qb * 128;
    size_t base = ((size_t)b * SEQ) * DM + h * HD;

    // ---- stage Q (fp32 -> split bf16), 128 rows x 64 d ----
    {
        int row = tid >> 1;
        int d0 = (tid & 1) * 32;
        const float* qg = q + base + (size_t)(i0 + row) * DM + d0;
        #pragma unroll
        for (int c = 0; c < 4; ++c) {
            float4 f0 = *(const float4*)(qg + c * 8);
            float4 f1 = *(const float4*)(qg + c * 8 + 4);
            uint4 hh, ll;
            split_pack(f0.x, f0.y, hh.x, ll.x);
            split_pack(f0.z, f0.w, hh.y, ll.y);
            split_pack(f1.x, f1.y, hh.z, ll.z);
            split_pack(f1.z, f1.w, hh.w, ll.w);
            int chunk = (d0 >> 3) + c;
            int off = row * 128 + ((chunk ^ (row & 7)) << 4);
            *(uint4*)(Qh + off) = hh;
            *(uint4*)(Ql + off) = ll;
        }
    }
    __syncthreads();

    // ---- hoisted Q A-fragments (rows 16*wid .. +15, all 64 d) ----
    int r0 = 16 * wid;
    unsigned aqh[4][4], aql[4][4];
    #pragma unroll
    for (int kc = 0; kc < 4; ++kc) {
        int m = lane >> 3;
        int lr = r0 + (lane & 7) + (m & 1) * 8;
        int lc = (2 * kc + (m >> 1)) ^ (lr & 7);
        ldmx4(aqh[kc], uQh + lr * 128 + lc * 16);
        ldmx4(aql[kc], uQl + lr * 128 + lc * 16);
    }

    float oacc[8][4];
    #pragma unroll
    for (int i = 0; i < 8; ++i)
        #pragma unroll
        for (int c = 0; c < 4; ++c) oacc[i][c] = 0.0f;
    float mrow0 = -1e30f, mrow1 = -1e30f;
    float lrow0 = 0.0f, lrow1 = 0.0f;

    int rowg0 = i0 + r0 + g;
    int ntiles = 2 * qb + 2;
    int nfull  = 2 * qb;

    for (int j = 0; j < ntiles; ++j) {
        __syncthreads();
        // ---- stage K, V tile j (64 rows x 64 d) ----
        {
            int row = tid >> 2;
            int d0 = (tid & 3) * 16;
            const float* kg = k + base + (size_t)(j * 64 + row) * DM + d0;
            const float* vg = v + base + (size_t)(j * 64 + row) * DM + d0;
            #pragma unroll
            for (int c = 0; c < 2; ++c) {
                float4 f0 = *(const float4*)(kg + c * 8);
                float4 f1 = *(const float4*)(kg + c * 8 + 4);
                uint4 hh, ll;
                split_pack(f0.x, f0.y, hh.x, ll.x);
                split_pack(f0.z, f0.w, hh.y, ll.y);
                split_pack(f1.x, f1.y, hh.z, ll.z);
                split_pack(f1.z, f1.w, hh.w, ll.w);
                int chunk = (d0 >> 3) + c;
                int off = row * 128 + ((chunk ^ (row & 7)) << 4);
                *(uint4*)(Kh + off) = hh;
                *(uint4*)(Kl + off) = ll;
                float4 g0 = *(const float4*)(vg + c * 8);
                float4 g1 = *(const float4*)(vg + c * 8 + 4);
                split_pack(g0.x, g0.y, hh.x, ll.x);
                split_pack(g0.z, g0.w, hh.y, ll.y);
                split_pack(g1.x, g1.y, hh.z, ll.z);
                split_pack(g1.z, g1.w, hh.w, ll.w);
                *(uint4*)(Vh + off) = hh;
                *(uint4*)(Vl + off) = ll;
            }
        }
        __syncthreads();

        // ---- S = Q K^T ----
        float sacc[8][4];
        #pragma unroll
        for (int i = 0; i < 8; ++i)
            #pragma unroll
            for (int c = 0; c < 4; ++c) sacc[i][c] = 0.0f;

        #pragma unroll
        for (int nt = 0; nt < 8; ++nt) {
            #pragma unroll
            for (int p = 0; p < 2; ++p) {
                int lr = 8 * nt + (lane & 7);
                int lc = (4 * p + (lane >> 3)) ^ (lr & 7);
                unsigned bkh[4], bkl[4];
                ldmx4(bkh, uKh + lr * 128 + lc * 16);
                ldmx4(bkl, uKl + lr * 128 + lc * 16);
                mma16(sacc[nt], aqh[2 * p],     bkh);
                mma16(sacc[nt], aql[2 * p],     bkh);
                mma16(sacc[nt], aqh[2 * p],     bkl);
                mma16(sacc[nt], aqh[2 * p + 1], bkh + 2);
                mma16(sacc[nt], aql[2 * p + 1], bkh + 2);
                mma16(sacc[nt], aqh[2 * p + 1], bkl + 2);
            }
        }

        // ---- scale + mask ----
        bool masked = (j >= nfull);
        int jb = j * 64;
        #pragma unroll
        for (int nt = 0; nt < 8; ++nt) {
            #pragma unroll
            for (int c = 0; c < 4; ++c) {
                float val = sacc[nt][c] * 0.125f;
                if (masked) {
                    int col = jb + 8 * nt + 2 * t + (c & 1);
                    int row = rowg0 + ((c >> 1) << 3);
                    if (col > row) val = -1e30f;
                }
                sacc[nt][c] = val;
            }
        }

        // ---- online softmax ----
        float m0 = -1e30f, m1 = -1e30f;
        #pragma unroll
        for (int nt = 0; nt < 8; ++nt) {
            m0 = fmaxf(m0, fmaxf(sacc[nt][0], sacc[nt][1]));
            m1 = fmaxf(m1, fmaxf(sacc[nt][2], sacc[nt][3]));
        }
        m0 = fmaxf(m0, __shfl_xor_sync(0xffffffffu, m0, 1));
        m0 = fmaxf(m0, __shfl_xor_sync(0xffffffffu, m0, 2));
        m1 = fmaxf(m1, __shfl_xor_sync(0xffffffffu, m1, 1));
        m1 = fmaxf(m1, __shfl_xor_sync(0xffffffffu, m1, 2));
        float mn0 = fmaxf(mrow0, m0);
        float mn1 = fmaxf(mrow1, m1);
        float corr0 = __expf(mrow0 - mn0);
        float corr1 = __expf(mrow1 - mn1);
        mrow0 = mn0; mrow1 = mn1;

        unsigned ph01[8], pl01[8], ph23[8], pl23[8];
        float rs0 = 0.0f, rs1 = 0.0f;
        #pragma unroll
        for (int nt = 0; nt < 8; ++nt) {
            float p0 = __expf(sacc[nt][0] - mn0);
            float p1 = __expf(sacc[nt][1] - mn0);
            float p2 = __expf(sacc[nt][2] - mn1);
            float p3 = __expf(sacc[nt][3] - mn1);
            rs0 += p0 + p1;
            rs1 += p2 + p3;
            split_pack(p0, p1, ph01[nt], pl01[nt]);
            split_pack(p2, p3, ph23[nt], pl23[nt]);
        }
        rs0 += __shfl_xor_sync(0xffffffffu, rs0, 1);
        rs0 += __shfl_xor_sync(0xffffffffu, rs0, 2);
        rs1 += __shfl_xor_sync(0xffffffffu, rs1, 1);
        rs1 += __shfl_xor_sync(0xffffffffu, rs1, 2);
        lrow0 = lrow0 * corr0 + rs0;
        lrow1 = lrow1 * corr1 + rs1;
        #pragma unroll
        for (int nd = 0; nd < 8; ++nd) {
            oacc[nd][0] *= corr0; oacc[nd][1] *= corr0;
            oacc[nd][2] *= corr1; oacc[nd][3] *= corr1;
        }

        // ---- O += P V ----
        #pragma unroll
        for (int kc = 0; kc < 4; ++kc) {
            unsigned pah[4] = { ph01[2 * kc], ph23[2 * kc],
                                ph01[2 * kc + 1], ph23[2 * kc + 1] };
            unsigned pal[4] = { pl01[2 * kc], pl23[2 * kc],
                                pl01[2 * kc + 1], pl23[2 * kc + 1] };
            #pragma unroll
            for (int nd2 = 0; nd2 < 4; ++nd2) {
                int lr = 16 * kc + (lane & 15);
                int lc = (2 * nd2 + (lane >> 4)) ^ (lr & 7);
                unsigned bvh[4], bvl[4];
                ldmx4t(bvh, uVh + lr * 128 + lc * 16);
                ldmx4t(bvl, uVl + lr * 128 + lc * 16);
                mma16(oacc[2 * nd2],     pah, bvh);
                mma16(oacc[2 * nd2],     pal, bvh);
                mma16(oacc[2 * nd2],     pah, bvl);
                mma16(oacc[2 * nd2 + 1], pah, bvh + 2);
                mma16(oacc[2 * nd2 + 1], pal, bvh + 2);
                mma16(oacc[2 * nd2 + 1], pah, bvl + 2);
            }
        }
    }

    // ---- epilogue: normalize, split to bf16 hi/lo, store ----
    float inv0 = 1.0f / lrow0;
    float inv1 = 1.0f / lrow1;
    #pragma unroll
    for (int nd = 0; nd < 8; ++nd) {
        int col = 8 * nd + 2 * t;
        size_t off0 = base + (size_t)(rowg0) * DM + col;
        size_t off1 = base + (size_t)(rowg0 + 8) * DM + col;
        unsigned hw, lw;
        split_pack(oacc[nd][0] * inv0, oacc[nd][1] * inv0, hw, lw);
        *(unsigned*)(aoh + off0) = hw;
        *(unsigned*)(aol + off0) = lw;
        split_pack(oacc[nd][2] * inv1, oacc[nd][3] * inv1, hw, lw);
        *(unsigned*)(aoh + off1) = hw;
        *(unsigned*)(aol + off1) = lw;
    }
}

// ---------------------------------------------------------------------------
// Launch
// ---------------------------------------------------------------------------
extern "C" void kernel_launch(void* const* d_in, const int* in_sizes, int n_in,
                              void* d_out, int out_size) {
    const float* x     = (const float*)d_in[0];
    const float* wq    = (const float*)d_in[1];
    const float* wk    = (const float*)d_in[2];
    const float* wv    = (const float*)d_in[3];
    const float* wo    = (const float*)d_in[4];
    const float* ln1w  = (const float*)d_in[5];
    const float* ln2w  = (const float*)d_in[6];
    const float* upw   = (const float*)d_in[7];
    const float* gatew = (const float*)d_in[8];
    const float* downw = (const float*)d_in[9];
    float* out = (float*)d_out;

    float *q, *k, *v, *x1, *gate;
    cudaGetSymbolAddress((void**)&q,    g_q);
    cudaGetSymbolAddress((void**)&k,    g_k);
    cudaGetSymbolAddress((void**)&v,    g_v);
    cudaGetSymbolAddress((void**)&x1,   g_x1);
    cudaGetSymbolAddress((void**)&gate, g_gate);

    bf16 *xnh, *xnl, *aoh, *aol, *hh, *hl;
    bf16 *wqh, *wql, *wkh, *wkl, *wvh, *wvl, *woh, *wol;
    bf16 *uph, *upl, *gwh, *gwl, *dwh, *dwl;
    cudaGetSymbolAddress((void**)&xnh, g_xnh);
    cudaGetSymbolAddress((void**)&xnl, g_xnl);
    cudaGetSymbolAddress((void**)&aoh, g_aoh);
    cudaGetSymbolAddress((void**)&aol, g_aol);
    cudaGetSymbolAddress((void**)&hh,  g_hh);
    cudaGetSymbolAddress((void**)&hl,  g_hl);
    cudaGetSymbolAddress((void**)&wqh, g_wqh);
    cudaGetSymbolAddress((void**)&wql, g_wql);
    cudaGetSymbolAddress((void**)&wkh, g_wkh);
    cudaGetSymbolAddress((void**)&wkl, g_wkl);
    cudaGetSymbolAddress((void**)&wvh, g_wvh);
    cudaGetSymbolAddress((void**)&wvl, g_wvl);
    cudaGetSymbolAddress((void**)&woh, g_woh);
    cudaGetSymbolAddress((void**)&wol, g_wol);
    cudaGetSymbolAddress((void**)&uph, g_uph);
    cudaGetSymbolAddress((void**)&upl, g_upl);
    cudaGetSymbolAddress((void**)&gwh, g_gwh);
    cudaGetSymbolAddress((void**)&gwl, g_gwl);
    cudaGetSymbolAddress((void**)&dwh, g_dwh);
    cudaGetSymbolAddress((void**)&dwl, g_dwl);

    cudaFuncSetAttribute(flash_kernel,
                         cudaFuncAttributeMaxDynamicSharedMemorySize, 65536);
    cudaFuncSetAttribute(bgemm_kernel<0>,
                         cudaFuncAttributeMaxDynamicSharedMemorySize, 65536);
    cudaFuncSetAttribute(bgemm_kernel<1>,
                         cudaFuncAttributeMaxDynamicSharedMemorySize, 65536);
    cudaFuncSetAttribute(bgemm_kernel<2>,
                         cudaFuncAttributeMaxDynamicSharedMemorySize, 65536);

    dim3 g1(DM / 128, M_ROWS / 128);    // (8, 64)
    dim3 g2(DFF / 128, M_ROWS / 128);   // (32, 64)

    // Weight splits
    split_kernel<<<DM * DM / 1024, 256>>>(wq, wqh, wql);
    split_kernel<<<DM * DM / 1024, 256>>>(wk, wkh, wkl);
    split_kernel<<<DM * DM / 1024, 256>>>(wv, wvh, wvl);
    split_kernel<<<DM * DM / 1024, 256>>>(wo, woh, wol);
    split_kernel<<<DFF * DM / 1024, 256>>>(upw, uph, upl);
    split_kernel<<<DFF * DM / 1024, 256>>>(gatew, gwh, gwl);
    split_kernel<<<DM * DFF / 1024, 256>>>(downw, dwh, dwl);

    // ln1 -> split xn
    rmsnorm_split_kernel<<<M_ROWS, 256>>>(x, ln1w, xnh, xnl);
    // q, k, v projections
    bgemm_kernel<0><<<g1, 256, 65536>>>(xnh, xnl, wqh, wql, q, nullptr, nullptr, nullptr, DM, DM);
    bgemm_kernel<0><<<g1, 256, 65536>>>(xnh, xnl, wkh, wkl, k, nullptr, nullptr, nullptr, DM, DM);
    bgemm_kernel<0><<<g1, 256, 65536>>>(xnh, xnl, wvh, wvl, v, nullptr, nullptr, nullptr, DM, DM);
    rope_kernel<<<(M_ROWS * 512) / 256, 256>>>(q, k);
    // tensor-core flash attention (writes split ao directly)
    flash_kernel<<<dim3(SEQ / 128, B_SZ * NHEAD), 256, 65536>>>(q, k, v, aoh, aol);
    // o projection + residual
    bgemm_kernel<1><<<g1, 256, 65536>>>(aoh, aol, woh, wol, x1, nullptr, nullptr, x, DM, DM);
    // ln2 -> split
    rmsnorm_split_kernel<<<M_ROWS, 256>>>(x1, ln2w, xnh, xnl);
    // FFN
    bgemm_kernel<0><<<g2, 256, 65536>>>(xnh, xnl, gwh, gwl, gate, nullptr, nullptr, nullptr, DFF, DM);
    bgemm_kernel<2><<<g2, 256, 65536>>>(xnh, xnl, uph, upl, nullptr, hh, hl, gate, DFF, DM);
    bgemm_kernel<1><<<g1, 256, 65536>>>(hh, hl, dwh, dwl, out, nullptr, nullptr, x1, DM, DFF);
}

// round 9
// speedup vs baseline: 2.2308x; 1.0281x over previous
#include <cuda_runtime.h>
#include <cuda_bf16.h>
#include <math.h>
#include <stdint.h>

// Problem constants
#define B_SZ 4
#define SEQ 2048
#define DM 1024
#define NHEAD 16
#define HD 64
#define DFF 4096
#define M_ROWS (B_SZ * SEQ)   // 8192

typedef __nv_bfloat16 bf16;

// ---------------------------------------------------------------------------
// Scratch buffers
// ---------------------------------------------------------------------------
__device__ float g_q[M_ROWS * DM];
__device__ float g_k[M_ROWS * DM];
__device__ float g_v[M_ROWS * DM];
__device__ float g_x1[M_ROWS * DM];
__device__ float g_gate[M_ROWS * DFF];

__device__ bf16 g_xnh[M_ROWS * DM],  g_xnl[M_ROWS * DM];
__device__ bf16 g_aoh[M_ROWS * DM],  g_aol[M_ROWS * DM];
__device__ bf16 g_hh[M_ROWS * DFF],  g_hl[M_ROWS * DFF];

__device__ bf16 g_wqh[DM * DM],   g_wql[DM * DM];
__device__ bf16 g_wkh[DM * DM],   g_wkl[DM * DM];
__device__ bf16 g_wvh[DM * DM],   g_wvl[DM * DM];
__device__ bf16 g_woh[DM * DM],   g_wol[DM * DM];
__device__ bf16 g_uph[DFF * DM],  g_upl[DFF * DM];
__device__ bf16 g_gwh[DFF * DM],  g_gwl[DFF * DM];
__device__ bf16 g_dwh[DM * DFF],  g_dwl[DM * DFF];

__device__ __forceinline__ void split1(float r, bf16* hi, bf16* lo, size_t off) {
    bf16 h = __float2bfloat16(r);
    hi[off] = h;
    lo[off] = __float2bfloat16(r - __bfloat162float(h));
}

__device__ __forceinline__ void split_pack(float f0, float f1,
                                           unsigned& h, unsigned& l) {
    bf16 h0 = __float2bfloat16(f0), h1 = __float2bfloat16(f1);
    unsigned short u0 = *(unsigned short*)&h0, u1 = *(unsigned short*)&h1;
    h = ((unsigned)u1 << 16) | u0;
    bf16 l0 = __float2bfloat16(f0 - __bfloat162float(h0));
    bf16 l1 = __float2bfloat16(f1 - __bfloat162float(h1));
    unsigned short v0 = *(unsigned short*)&l0, v1 = *(unsigned short*)&l1;
    l = ((unsigned)v1 << 16) | v0;
}

// ---------------------------------------------------------------------------
// Split fp32 -> (hi, lo) bf16 pair.
// ---------------------------------------------------------------------------
__global__ __launch_bounds__(256)
void split_kernel(const float* __restrict__ src, bf16* __restrict__ hi,
                  bf16* __restrict__ lo) {
    size_t i = ((size_t)blockIdx.x * 256 + threadIdx.x) * 4;
    float4 v = *(const float4*)(src + i);
    split1(v.x, hi, lo, i + 0);
    split1(v.y, hi, lo, i + 1);
    split1(v.z, hi, lo, i + 2);
    split1(v.w, hi, lo, i + 3);
}

// ---------------------------------------------------------------------------
// RMSNorm with split output
// ---------------------------------------------------------------------------
__global__ __launch_bounds__(256)
void rmsnorm_split_kernel(const float* __restrict__ x,
                          const float* __restrict__ w,
                          bf16* __restrict__ hi, bf16* __restrict__ lo) {
    int row = blockIdx.x;
    int tid = threadIdx.x;
    const float* xr = x + (size_t)row * DM;
    float4 v = *(const float4*)(xr + tid * 4);
    float s = v.x * v.x + v.y * v.y + v.z * v.z + v.w * v.w;
    #pragma unroll
    for (int off = 16; off; off >>= 1)
        s += __shfl_xor_sync(0xffffffffu, s, off);
    __shared__ float red[8];
    if ((tid & 31) == 0) red[tid >> 5] = s;
    __syncthreads();
    float tot = red[0] + red[1] + red[2] + red[3] +
                red[4] + red[5] + red[6] + red[7];
    float inv = rsqrtf(tot * (1.0f / DM) + 1e-5f);
    float4 wv = *(const float4*)(w + tid * 4);
    size_t o = (size_t)row * DM + tid * 4;
    split1(v.x * inv * wv.x, hi, lo, o + 0);
    split1(v.y * inv * wv.y, hi, lo, o + 1);
    split1(v.z * inv * wv.z, hi, lo, o + 2);
    split1(v.w * inv * wv.w, hi, lo, o + 3);
}

// ---------------------------------------------------------------------------
// RoPE in-place on q and k (fp32).
// ---------------------------------------------------------------------------
__global__ __launch_bounds__(256)
void rope_kernel(float* __restrict__ q, float* __restrict__ k) {
    int idx = blockIdx.x * blockDim.x + threadIdx.x;
    if (idx >= M_ROWS * 512) return;
    int m  = idx >> 9;
    int pir = idx & 511;
    int h  = pir >> 5;
    int pp = pir & 31;
    int s  = m & (SEQ - 1);
    float inv_freq = expf(-(float)(2 * pp) * (9.210340371976184f / 64.0f));
    float ang = (float)s * inv_freq;
    float sn, cs;
    sincosf(ang, &sn, &cs);
    size_t off = (size_t)m * DM + h * HD + 2 * pp;
    float qe = q[off], qo = q[off + 1];
    q[off]     = qe * cs - qo * sn;
    q[off + 1] = qo * cs + qe * sn;
    float ke = k[off], ko = k[off + 1];
    k[off]     = ke * cs - ko * sn;
    k[off + 1] = ko * cs + ke * sn;
}

// ---------------------------------------------------------------------------
// mma / ldmatrix / cp.async primitives
// ---------------------------------------------------------------------------
__device__ __forceinline__ void mma16(float* d, const unsigned* a,
                                      const unsigned* b) {
    asm volatile(
        "mma.sync.aligned.m16n8k16.row.col.f32.bf16.bf16.f32 "
        "{%0,%1,%2,%3}, {%4,%5,%6,%7}, {%8,%9}, {%0,%1,%2,%3};"
        : "+f"(d[0]), "+f"(d[1]), "+f"(d[2]), "+f"(d[3])
        : "r"(a[0]), "r"(a[1]), "r"(a[2]), "r"(a[3]), "r"(b[0]), "r"(b[1]));
}
__device__ __forceinline__ void ldmx4(unsigned* r, uint32_t addr) {
    asm volatile(
        "ldmatrix.sync.aligned.m8n8.x4.shared.b16 {%0,%1,%2,%3}, [%4];"
        : "=r"(r[0]), "=r"(r[1]), "=r"(r[2]), "=r"(r[3]) : "r"(addr));
}
__device__ __forceinline__ void ldmx4t(unsigned* r, uint32_t addr) {
    asm volatile(
        "ldmatrix.sync.aligned.m8n8.x4.trans.shared.b16 {%0,%1,%2,%3}, [%4];"
        : "=r"(r[0]), "=r"(r[1]), "=r"(r[2]), "=r"(r[3]) : "r"(addr));
}
__device__ __forceinline__ void cp_async16(uint32_t s, const void* g) {
    asm volatile("cp.async.cg.shared.global [%0], [%1], 16;\n"
                 :: "r"(s), "l"(g));
}
__device__ __forceinline__ void cp_commit() {
    asm volatile("cp.async.commit_group;\n");
}
__device__ __forceinline__ void cp_wait0() {
    asm volatile("cp.async.wait_group 0;\n");
}

// ---------------------------------------------------------------------------
// bf16 split-compensated GEMM with ldmatrix fragment loads.
// C[M,N] = A[M,K] * W[N,K]^T (+epilogue); D += Ah*Wh + Al*Wh + Ah*Wl.
// 128x128x32 tile, 256 thr (8 warps 2x4, 64x32 warp tile), mma.m16n8k16.
// Smem row: 32 bf16 = 64B = 4 chunks of 16B, chunk' = chunk ^ ((row>>1)&3).
// EPI: 0 C=AB; 1 C=AB+aux; 2 (Ch,Cl)=split(silu(AB)*aux)
// ---------------------------------------------------------------------------
template <int EPI>
__global__ __launch_bounds__(256, 1)
void bgemm_kernel(const bf16* __restrict__ Ah, const bf16* __restrict__ Al,
                  const bf16* __restrict__ Wh, const bf16* __restrict__ Wl,
                  float* __restrict__ C, bf16* __restrict__ Ch,
                  bf16* __restrict__ Cl, const float* __restrict__ aux,
                  int N, int K) {
    extern __shared__ char smc[];
    int tid = threadIdx.x;
    int wid = tid >> 5, lane = tid & 31;
    int g = lane >> 2, t = lane & 3;
    int wm = wid >> 2, wn = wid & 3;
    int m0 = blockIdx.y * 128;
    int n0 = blockIdx.x * 128;

    uint32_t smem_base = (uint32_t)__cvta_generic_to_shared(smc);

    // ldmatrix lane roles (precomputed):
    // A x4: m0=(r,k0) m1=(r+8,k0) m2=(r,k1) m3=(r+8,k1)
    int mm = lane >> 3;
    int aRowLoc = (mm & 1) * 8 + (lane & 7);
    int aCb = mm >> 1;
    // B x4: m0=(n,k0) m1=(n,k1) m2=(n+8,k0) m3=(n+8,k1)
    int bRowLoc = (mm >> 1) * 8 + (lane & 7);
    int bCb = mm & 1;

    uint32_t aOff[4]; int aSw[4];
    #pragma unroll
    for (int mt = 0; mt < 4; ++mt) {
        int r = wm * 64 + mt * 16 + aRowLoc;
        aOff[mt] = r * 64;
        aSw[mt] = (r >> 1) & 3;
    }
    uint32_t bOff[2]; int bSw[2];
    #pragma unroll
    for (int nt2 = 0; nt2 < 2; ++nt2) {
        int r = wn * 32 + nt2 * 16 + bRowLoc;
        bOff[nt2] = r * 64;
        bSw[nt2] = (r >> 1) & 3;
    }

    float acc[4][4][4];
    #pragma unroll
    for (int i = 0; i < 4; ++i)
        #pragma unroll
        for (int j = 0; j < 4; ++j)
            #pragma unroll
            for (int c = 0; c < 4; ++c) acc[i][j][c] = 0.0f;

    int niter = K >> 5;
    int grow = tid >> 1;
    int gch0 = (tid & 1) << 1;

    #define STAGE(buf, k0)                                                      \
    {                                                                           \
        _Pragma("unroll")                                                       \
        for (int cc = 0; cc < 2; ++cc) {                                        \
            int ch = gch0 + cc;                                                 \
            uint32_t soff = (uint32_t)(grow * 64 +                              \
                ((ch ^ ((grow >> 1) & 3)) << 4));                               \
            size_t ga = (size_t)(m0 + grow) * K + (k0) + ch * 8;                \
            size_t gb = (size_t)(n0 + grow) * K + (k0) + ch * 8;                \
            uint32_t sb = smem_base + (buf) * 32768 + soff;                     \
            cp_async16(sb,         Ah + ga);                                    \
            cp_async16(sb + 8192,  Al + ga);                                    \
            cp_async16(sb + 16384, Wh + gb);                                    \
            cp_async16(sb + 24576, Wl + gb);                                    \
        }                                                                       \
        cp_commit();                                                            \
    }

    STAGE(0, 0);
    cp_wait0();
    __syncthreads();

    int buf = 0;
    for (int it = 0; it < niter; ++it) {
        if (it + 1 < niter) STAGE(buf ^ 1, (it + 1) << 5);

        uint32_t tAh = smem_base + buf * 32768;
        uint32_t tAl = tAh + 8192;
        uint32_t tBh = tAh + 16384;
        uint32_t tBl = tAh + 24576;

        #pragma unroll
        for (int ck = 0; ck < 2; ++ck) {
            unsigned bhf[2][4], blf[2][4];
            #pragma unroll
            for (int nt2 = 0; nt2 < 2; ++nt2) {
                uint32_t off = bOff[nt2] +
                               (((2 * ck + bCb) ^ bSw[nt2]) << 4);
                ldmx4(bhf[nt2], tBh + off);
                ldmx4(blf[nt2], tBl + off);
            }
            #pragma unroll
            for (int mt = 0; mt < 4; ++mt) {
                uint32_t off = aOff[mt] +
                               (((2 * ck + aCb) ^ aSw[mt]) << 4);
                unsigned ah[4], al[4];
                ldmx4(ah, tAh + off);
                ldmx4(al, tAl + off);
                #pragma unroll
                for (int nt2 = 0; nt2 < 2; ++nt2) {
                    mma16(acc[mt][2 * nt2],     ah, bhf[nt2]);
                    mma16(acc[mt][2 * nt2],     al, bhf[nt2]);
                    mma16(acc[mt][2 * nt2],     ah, blf[nt2]);
                    mma16(acc[mt][2 * nt2 + 1], ah, bhf[nt2] + 2);
                    mma16(acc[mt][2 * nt2 + 1], al, bhf[nt2] + 2);
                    mma16(acc[mt][2 * nt2 + 1], ah, blf[nt2] + 2);
                }
            }
        }

        if (it + 1 < niter) cp_wait0();
        __syncthreads();
        buf ^= 1;
    }
    #undef STAGE

    #pragma unroll
    for (int mt = 0; mt < 4; ++mt) {
        #pragma unroll
        for (int nt = 0; nt < 4; ++nt) {
            int rb = m0 + wm * 64 + mt * 16 + g;
            int cb = n0 + wn * 32 + nt * 8 + 2 * t;
            #pragma unroll
            for (int half = 0; half < 2; ++half) {
                size_t off = (size_t)(rb + half * 8) * N + cb;
                #pragma unroll
                for (int e = 0; e < 2; ++e) {
                    float u = acc[mt][nt][half * 2 + e];
                    if (EPI == 0) {
                        C[off + e] = u;
                    } else if (EPI == 1) {
                        C[off + e] = u + aux[off + e];
                    } else {
                        float sg = 1.0f / (1.0f + __expf(-u));
                        float r = u * sg * aux[off + e];
                        split1(r, Ch, Cl, off + e);
                    }
                }
            }
        }
    }
}

// ---------------------------------------------------------------------------
// Tensor-core flash attention (causal), bf16 split-compensated. (round 6)
// ---------------------------------------------------------------------------
__global__ __launch_bounds__(256, 1)
void flash_kernel(const float* __restrict__ q, const float* __restrict__ k,
                  const float* __restrict__ v,
                  bf16* __restrict__ aoh, bf16* __restrict__ aol) {
    extern __shared__ char sm[];
    char* Qh = sm;
    char* Ql = sm + 16384;
    char* Kh = sm + 32768;
    char* Kl = sm + 40960;
    char* Vh = sm + 49152;
    char* Vl = sm + 57344;
    uint32_t uQh = (uint32_t)__cvta_generic_to_shared(Qh);
    uint32_t uQl = uQh + 16384;
    uint32_t uKh = uQh + 32768;
    uint32_t uKl = uQh + 40960;
    uint32_t uVh = uQh + 49152;
    uint32_t uVl = uQh + 57344;

    int tid = threadIdx.x;
    int wid = tid >> 5, lane = tid & 31;
    int g = lane >> 2, t = lane & 3;
    int qb = blockIdx.x;
    int bh = blockIdx.y;
    int b = bh >> 4, h = bh & 15;
    int i0 = qb * 128;
    size_t base = ((size_t)b * SEQ) * DM + h * HD;

    {
        int row = tid >> 1;
        int d0 = (tid & 1) * 32;
        const float* qg = q + base + (size_t)(i0 + row) * DM + d0;
        #pragma unroll
        for (int c = 0; c < 4; ++c) {
            float4 f0 = *(const float4*)(qg + c * 8);
            float4 f1 = *(const float4*)(qg + c * 8 + 4);
            uint4 hh, ll;
            split_pack(f0.x, f0.y, hh.x, ll.x);
            split_pack(f0.z, f0.w, hh.y, ll.y);
            split_pack(f1.x, f1.y, hh.z, ll.z);
            split_pack(f1.z, f1.w, hh.w, ll.w);
            int chunk = (d0 >> 3) + c;
            int off = row * 128 + ((chunk ^ (row & 7)) << 4);
            *(uint4*)(Qh + off) = hh;
            *(uint4*)(Ql + off) = ll;
        }
    }
    __syncthreads();

    int r0 = 16 * wid;
    unsigned aqh[4][4], aql[4][4];
    #pragma unroll
    for (int kc = 0; kc < 4; ++kc) {
        int m = lane >> 3;
        int lr = r0 + (lane & 7) + (m & 1) * 8;
        int lc = (2 * kc + (m >> 1)) ^ (lr & 7);
        ldmx4(aqh[kc], uQh + lr * 128 + lc * 16);
        ldmx4(aql[kc], uQl + lr * 128 + lc * 16);
    }

    float oacc[8][4];
    #pragma unroll
    for (int i = 0; i < 8; ++i)
        #pragma unroll
        for (int c = 0; c < 4; ++c) oacc[i][c] = 0.0f;
    float mrow0 = -1e30f, mrow1 = -1e30f;
    float lrow0 = 0.0f, lrow1 = 0.0f;

    int rowg0 = i0 + r0 + g;
    int ntiles = 2 * qb + 2;
    int nfull  = 2 * qb;

    for (int j = 0; j < ntiles; ++j) {
        __syncthreads();
        {
            int row = tid >> 2;
            int d0 = (tid & 3) * 16;
            const float* kg = k + base + (size_t)(j * 64 + row) * DM + d0;
            const float* vg = v + base + (size_t)(j * 64 + row) * DM + d0;
            #pragma unroll
            for (int c = 0; c < 2; ++c) {
                float4 f0 = *(const float4*)(kg + c * 8);
                float4 f1 = *(const float4*)(kg + c * 8 + 4);
                uint4 hh, ll;
                split_pack(f0.x, f0.y, hh.x, ll.x);
                split_pack(f0.z, f0.w, hh.y, ll.y);
                split_pack(f1.x, f1.y, hh.z, ll.z);
                split_pack(f1.z, f1.w, hh.w, ll.w);
                int chunk = (d0 >> 3) + c;
                int off = row * 128 + ((chunk ^ (row & 7)) << 4);
                *(uint4*)(Kh + off) = hh;
                *(uint4*)(Kl + off) = ll;
                float4 g0 = *(const float4*)(vg + c * 8);
                float4 g1 = *(const float4*)(vg + c * 8 + 4);
                split_pack(g0.x, g0.y, hh.x, ll.x);
                split_pack(g0.z, g0.w, hh.y, ll.y);
                split_pack(g1.x, g1.y, hh.z, ll.z);
                split_pack(g1.z, g1.w, hh.w, ll.w);
                *(uint4*)(Vh + off) = hh;
                *(uint4*)(Vl + off) = ll;
            }
        }
        __syncthreads();

        float sacc[8][4];
        #pragma unroll
        for (int i = 0; i < 8; ++i)
            #pragma unroll
            for (int c = 0; c < 4; ++c) sacc[i][c] = 0.0f;

        #pragma unroll
        for (int nt = 0; nt < 8; ++nt) {
            #pragma unroll
            for (int p = 0; p < 2; ++p) {
                int lr = 8 * nt + (lane & 7);
                int lc = (4 * p + (lane >> 3)) ^ (lr & 7);
                unsigned bkh[4], bkl[4];
                ldmx4(bkh, uKh + lr * 128 + lc * 16);
                ldmx4(bkl, uKl + lr * 128 + lc * 16);
                mma16(sacc[nt], aqh[2 * p],     bkh);
                mma16(sacc[nt], aql[2 * p],     bkh);
                mma16(sacc[nt], aqh[2 * p],     bkl);
                mma16(sacc[nt], aqh[2 * p + 1], bkh + 2);
                mma16(sacc[nt], aql[2 * p + 1], bkh + 2);
                mma16(sacc[nt], aqh[2 * p + 1], bkl + 2);
            }
        }

        bool masked = (j >= nfull);
        int jb = j * 64;
        #pragma unroll
        for (int nt = 0; nt < 8; ++nt) {
            #pragma unroll
            for (int c = 0; c < 4; ++c) {
                float val = sacc[nt][c] * 0.125f;
                if (masked) {
                    int col = jb + 8 * nt + 2 * t + (c & 1);
                    int row = rowg0 + ((c >> 1) << 3);
                    if (col > row) val = -1e30f;
                }
                sacc[nt][c] = val;
            }
        }

        float m0 = -1e30f, m1 = -1e30f;
        #pragma unroll
        for (int nt = 0; nt < 8; ++nt) {
            m0 = fmaxf(m0, fmaxf(sacc[nt][0], sacc[nt][1]));
            m1 = fmaxf(m1, fmaxf(sacc[nt][2], sacc[nt][3]));
        }
        m0 = fmaxf(m0, __shfl_xor_sync(0xffffffffu, m0, 1));
        m0 = fmaxf(m0, __shfl_xor_sync(0xffffffffu, m0, 2));
        m1 = fmaxf(m1, __shfl_xor_sync(0xffffffffu, m1, 1));
        m1 = fmaxf(m1, __shfl_xor_sync(0xffffffffu, m1, 2));
        float mn0 = fmaxf(mrow0, m0);
        float mn1 = fmaxf(mrow1, m1);
        float corr0 = __expf(mrow0 - mn0);
        float corr1 = __expf(mrow1 - mn1);
        mrow0 = mn0; mrow1 = mn1;

        unsigned ph01[8], pl01[8], ph23[8], pl23[8];
        float rs0 = 0.0f, rs1 = 0.0f;
        #pragma unroll
        for (int nt = 0; nt < 8; ++nt) {
            float p0 = __expf(sacc[nt][0] - mn0);
            float p1 = __expf(sacc[nt][1] - mn0);
            float p2 = __expf(sacc[nt][2] - mn1);
            float p3 = __expf(sacc[nt][3] - mn1);
            rs0 += p0 + p1;
            rs1 += p2 + p3;
            split_pack(p0, p1, ph01[nt], pl01[nt]);
            split_pack(p2, p3, ph23[nt], pl23[nt]);
        }
        rs0 += __shfl_xor_sync(0xffffffffu, rs0, 1);
        rs0 += __shfl_xor_sync(0xffffffffu, rs0, 2);
        rs1 += __shfl_xor_sync(0xffffffffu, rs1, 1);
        rs1 += __shfl_xor_sync(0xffffffffu, rs1, 2);
        lrow0 = lrow0 * corr0 + rs0;
        lrow1 = lrow1 * corr1 + rs1;
        #pragma unroll
        for (int nd = 0; nd < 8; ++nd) {
            oacc[nd][0] *= corr0; oacc[nd][1] *= corr0;
            oacc[nd][2] *= corr1; oacc[nd][3] *= corr1;
        }

        #pragma unroll
        for (int kc = 0; kc < 4; ++kc) {
            unsigned pah[4] = { ph01[2 * kc], ph23[2 * kc],
                                ph01[2 * kc + 1], ph23[2 * kc + 1] };
            unsigned pal[4] = { pl01[2 * kc], pl23[2 * kc],
                                pl01[2 * kc + 1], pl23[2 * kc + 1] };
            #pragma unroll
            for (int nd2 = 0; nd2 < 4; ++nd2) {
                int lr = 16 * kc + (lane & 15);
                int lc = (2 * nd2 + (lane >> 4)) ^ (lr & 7);
                unsigned bvh[4], bvl[4];
                ldmx4t(bvh, uVh + lr * 128 + lc * 16);
                ldmx4t(bvl, uVl + lr * 128 + lc * 16);
                mma16(oacc[2 * nd2],     pah, bvh);
                mma16(oacc[2 * nd2],     pal, bvh);
                mma16(oacc[2 * nd2],     pah, bvl);
                mma16(oacc[2 * nd2 + 1], pah, bvh + 2);
                mma16(oacc[2 * nd2 + 1], pal, bvh + 2);
                mma16(oacc[2 * nd2 + 1], pah, bvl + 2);
            }
        }
    }

    float inv0 = 1.0f / lrow0;
    float inv1 = 1.0f / lrow1;
    #pragma unroll
    for (int nd = 0; nd < 8; ++nd) {
        int col = 8 * nd + 2 * t;
        size_t off0 = base + (size_t)(rowg0) * DM + col;
        size_t off1 = base + (size_t)(rowg0 + 8) * DM + col;
        unsigned hw, lw;
        split_pack(oacc[nd][0] * inv0, oacc[nd][1] * inv0, hw, lw);
        *(unsigned*)(aoh + off0) = hw;
        *(unsigned*)(aol + off0) = lw;
        split_pack(oacc[nd][2] * inv1, oacc[nd][3] * inv1, hw, lw);
        *(unsigned*)(aoh + off1) = hw;
        *(unsigned*)(aol + off1) = lw;
    }
}

// ---------------------------------------------------------------------------
// Launch
// ---------------------------------------------------------------------------
extern "C" void kernel_launch(void* const* d_in, const int* in_sizes, int n_in,
                              void* d_out, int out_size) {
    const float* x     = (const float*)d_in[0];
    const float* wq    = (const float*)d_in[1];
    const float* wk    = (const float*)d_in[2];
    const float* wv    = (const float*)d_in[3];
    const float* wo    = (const float*)d_in[4];
    const float* ln1w  = (const float*)d_in[5];
    const float* ln2w  = (const float*)d_in[6];
    const float* upw   = (const float*)d_in[7];
    const float* gatew = (const float*)d_in[8];
    const float* downw = (const float*)d_in[9];
    float* out = (float*)d_out;

    float *q, *k, *v, *x1, *gate;
    cudaGetSymbolAddress((void**)&q,    g_q);
    cudaGetSymbolAddress((void**)&k,    g_k);
    cudaGetSymbolAddress((void**)&v,    g_v);
    cudaGetSymbolAddress((void**)&x1,   g_x1);
    cudaGetSymbolAddress((void**)&gate, g_gate);

    bf16 *xnh, *xnl, *aoh, *aol, *hh, *hl;
    bf16 *wqh, *wql, *wkh, *wkl, *wvh, *wvl, *woh, *wol;
    bf16 *uph, *upl, *gwh, *gwl, *dwh, *dwl;
    cudaGetSymbolAddress((void**)&xnh, g_xnh);
    cudaGetSymbolAddress((void**)&xnl, g_xnl);
    cudaGetSymbolAddress((void**)&aoh, g_aoh);
    cudaGetSymbolAddress((void**)&aol, g_aol);
    cudaGetSymbolAddress((void**)&hh,  g_hh);
    cudaGetSymbolAddress((void**)&hl,  g_hl);
    cudaGetSymbolAddress((void**)&wqh, g_wqh);
    cudaGetSymbolAddress((void**)&wql, g_wql);
    cudaGetSymbolAddress((void**)&wkh, g_wkh);
    cudaGetSymbolAddress((void**)&wkl, g_wkl);
    cudaGetSymbolAddress((void**)&wvh, g_wvh);
    cudaGetSymbolAddress((void**)&wvl, g_wvl);
    cudaGetSymbolAddress((void**)&woh, g_woh);
    cudaGetSymbolAddress((void**)&wol, g_wol);
    cudaGetSymbolAddress((void**)&uph, g_uph);
    cudaGetSymbolAddress((void**)&upl, g_upl);
    cudaGetSymbolAddress((void**)&gwh, g_gwh);
    cudaGetSymbolAddress((void**)&gwl, g_gwl);
    cudaGetSymbolAddress((void**)&dwh, g_dwh);
    cudaGetSymbolAddress((void**)&dwl, g_dwl);

    cudaFuncSetAttribute(flash_kernel,
                         cudaFuncAttributeMaxDynamicSharedMemorySize, 65536);
    cudaFuncSetAttribute(bgemm_kernel<0>,
                         cudaFuncAttributeMaxDynamicSharedMemorySize, 65536);
    cudaFuncSetAttribute(bgemm_kernel<1>,
                         cudaFuncAttributeMaxDynamicSharedMemorySize, 65536);
    cudaFuncSetAttribute(bgemm_kernel<2>,
                         cudaFuncAttributeMaxDynamicSharedMemorySize, 65536);

    dim3 g1(DM / 128, M_ROWS / 128);    // (8, 64)
    dim3 g2(DFF / 128, M_ROWS / 128);   // (32, 64)

    // Weight splits
    split_kernel<<<DM * DM / 1024, 256>>>(wq, wqh, wql);
    split_kernel<<<DM * DM / 1024, 256>>>(wk, wkh, wkl);
    split_kernel<<<DM * DM / 1024, 256>>>(wv, wvh, wvl);
    split_kernel<<<DM * DM / 1024, 256>>>(wo, woh, wol);
    split_kernel<<<DFF * DM / 1024, 256>>>(upw, uph, upl);
    split_kernel<<<DFF * DM / 1024, 256>>>(gatew, gwh, gwl);
    split_kernel<<<DM * DFF / 1024, 256>>>(downw, dwh, dwl);

    // ln1 -> split xn
    rmsnorm_split_kernel<<<M_ROWS, 256>>>(x, ln1w, xnh, xnl);
    // q, k, v projections
    bgemm_kernel<0><<<g1, 256, 65536>>>(xnh, xnl, wqh, wql, q, nullptr, nullptr, nullptr, DM, DM);
    bgemm_kernel<0><<<g1, 256, 65536>>>(xnh, xnl, wkh, wkl, k, nullptr, nullptr, nullptr, DM, DM);
    bgemm_kernel<0><<<g1, 256, 65536>>>(xnh, xnl, wvh, wvl, v, nullptr, nullptr, nullptr, DM, DM);
    rope_kernel<<<(M_ROWS * 512) / 256, 256>>>(q, k);
    // tensor-core flash attention (writes split ao directly)
    flash_kernel<<<dim3(SEQ / 128, B_SZ * NHEAD), 256, 65536>>>(q, k, v, aoh, aol);
    // o projection + residual
    bgemm_kernel<1><<<g1, 256, 65536>>>(aoh, aol, woh, wol, x1, nullptr, nullptr, x, DM, DM);
    // ln2 -> split
    rmsnorm_split_kernel<<<M_ROWS, 256>>>(x1, ln2w, xnh, xnl);
    // FFN
    bgemm_kernel<0><<<g2, 256, 65536>>>(xnh, xnl, gwh, gwl, gate, nullptr, nullptr, nullptr, DFF, DM);
    bgemm_kernel<2><<<g2, 256, 65536>>>(xnh, xnl, uph, upl, nullptr, hh, hl, gate, DFF, DM);
    bgemm_kernel<1><<<g1, 256, 65536>>>(hh, hl, dwh, dwl, out, nullptr, nullptr, x1, DM, DFF);
}